// round 3
// baseline (speedup 1.0000x reference)
#include <cuda_runtime.h>
#include <cuda_bf16.h>
#include <cstdint>

// ============================================================================
// IDCST2: out = C0 @ x @ S1^T, M=N=4096 fp32.
// ptxas target is plain sm_103 (no 'a') -> tcgen05 unavailable. Use baseline
// PTX tensor path: mma.sync.m16n8k16 bf16 + ldmatrix + cp.async pipeline.
// Precision: 3-term bf16 split per GEMM (Ah*Bh + Ah*Bl + Al*Bh, fp32 accum).
// GEMM1: Yt[v,p] = sum_q S1[v,q] x[p,q]   (A=S1, B=x, direct row-major store,
//                                          epilogue re-splits Yt to bf16 h/l)
// GEMM2: out[u,v] = sum_p C0[u,p] Yt[v,p] (A=C0, B=Yt, direct fp32 store)
// Bases generated from a 16384-entry sin table (phases exact mod 16384).
// ============================================================================

#define NDIM 4096
typedef __nv_bfloat16 bf16;

static constexpr int BM = 128;
static constexpr int BN = 128;
static constexpr int BK = 32;
static constexpr int KT = NDIM / BK;       // 128 k-tiles

static constexpr int ROWB        = 80;             // padded smem row stride (bytes)
static constexpr int PLANE_BYTES = 128 * ROWB;     // 10240
static constexpr int STAGE_BYTES = 4 * PLANE_BYTES;// 40960 (Ah,Al,Bh,Bl)
static constexpr int SMEM_BYTES  = 2 * STAGE_BYTES;// 81920 (double buffer)

// -------------------- device scratch (module-load allocations) --------------
__device__ float g_table[16384];
__device__ bf16 g_xh[(size_t)NDIM * NDIM];
__device__ bf16 g_xl[(size_t)NDIM * NDIM];
__device__ bf16 g_S1h[(size_t)NDIM * NDIM];
__device__ bf16 g_S1l[(size_t)NDIM * NDIM];
__device__ bf16 g_C0h[(size_t)NDIM * NDIM];
__device__ bf16 g_C0l[(size_t)NDIM * NDIM];
__device__ bf16 g_Yth[(size_t)NDIM * NDIM];
__device__ bf16 g_Ytl[(size_t)NDIM * NDIM];

// -------------------- small helpers -----------------------------------------
__device__ __forceinline__ uint32_t smem_to_u32(const void* p) {
    uint32_t a;
    asm("{ .reg .u64 t; cvta.to.shared.u64 t, %1; cvt.u32.u64 %0, t; }" : "=r"(a) : "l"(p));
    return a;
}

// split (x,y) fp32 pair into bf16 hi-pair and lo-pair (packed u32 each)
__device__ __forceinline__ void split_pair(float x, float y, uint32_t& h, uint32_t& l) {
    __nv_bfloat162 H = __floats2bfloat162_rn(x, y);
    float2 F = __bfloat1622float2(H);
    __nv_bfloat162 L = __floats2bfloat162_rn(x - F.x, y - F.y);
    h = *(uint32_t*)&H;
    l = *(uint32_t*)&L;
}

#define CP_ASYNC16(dst, src) \
    asm volatile("cp.async.cg.shared.global [%0], [%1], 16;" :: "r"(dst), "l"(src))
#define CP_COMMIT() asm volatile("cp.async.commit_group;" ::: "memory")
#define CP_WAIT1()  asm volatile("cp.async.wait_group 1;"  ::: "memory")

#define LDSM4(r, addr) \
    asm volatile("ldmatrix.sync.aligned.m8n8.x4.shared.b16 {%0,%1,%2,%3}, [%4];" \
                 : "=r"((r)[0]), "=r"((r)[1]), "=r"((r)[2]), "=r"((r)[3]) : "r"(addr))

#define MMA16816(d, a, b0, b1) \
    asm volatile("mma.sync.aligned.m16n8k16.row.col.f32.bf16.bf16.f32 " \
                 "{%0,%1,%2,%3}, {%4,%5,%6,%7}, {%8,%9}, {%0,%1,%2,%3};" \
                 : "+f"((d)[0]), "+f"((d)[1]), "+f"((d)[2]), "+f"((d)[3]) \
                 : "r"((a)[0]), "r"((a)[1]), "r"((a)[2]), "r"((a)[3]), "r"(b0), "r"(b1))

// ---------------------------------------------------------------------------
// sin table: g_table[r] = sin(pi * r / 8192), r in [0, 16384)
// C0[u,p] = cos(pi*(2u+1)p/8192) = table[((2u+1)p + 4096) mod 16384]
// S1[v,q] = sin(pi*(2v+1)q/8192) = table[((2v+1)q) mod 16384]
// ---------------------------------------------------------------------------
__global__ void build_table_kernel() {
    int r = blockIdx.x * 256 + threadIdx.x;  // < 16384
    float s, c;
    sincospif((float)r * (1.0f / 8192.0f), &s, &c);
    g_table[r] = s;
}

// Each thread handles 2 consecutive j, writes packed bf16x2 to all 4 planes.
__global__ void gen_basis_kernel() {
    int t = blockIdx.x * 256 + threadIdx.x;   // 8.39M threads
    int i = t >> 11;                           // row 0..4095
    int j = (t & 2047) << 1;                   // even col
    int step = 2 * i + 1;
    int a0 = (step * j) & 16383;
    int a1 = (a0 + step) & 16383;
    float s0 = g_table[a0];
    float s1 = g_table[a1];
    float c0 = g_table[(a0 + 4096) & 16383];
    float c1 = g_table[(a1 + 4096) & 16383];
    size_t off = ((size_t)i << 12) + j;
    uint32_t h, l;
    split_pair(s0, s1, h, l);
    *(uint32_t*)(g_S1h + off) = h;
    *(uint32_t*)(g_S1l + off) = l;
    split_pair(c0, c1, h, l);
    *(uint32_t*)(g_C0h + off) = h;
    *(uint32_t*)(g_C0l + off) = l;
}

__global__ void split_x_kernel(const float4* __restrict__ x) {
    int t = blockIdx.x * 256 + threadIdx.x;   // 4.19M threads, 4 floats each
    float4 v = x[t];
    uint32_t h01, l01, h23, l23;
    split_pair(v.x, v.y, h01, l01);
    split_pair(v.z, v.w, h23, l23);
    ((uint2*)g_xh)[t] = make_uint2(h01, h23);
    ((uint2*)g_xl)[t] = make_uint2(l01, l23);
}

// ---------------------------------------------------------------------------
// GEMM: D[m,n] = sum_k A[m,k] * B[n,k], all operands bf16 split (h/l planes).
// epi=0: store fp32 to outF.  epi=1: store bf16 split (outH/outL).
// ---------------------------------------------------------------------------
__device__ __forceinline__ void load_stage(const bf16* const (&gsrc)[4],
                                           uint32_t sdst, int st, int kt) {
    #pragma unroll
    for (int p = 0; p < 4; ++p) {
        const bf16* s0 = gsrc[p] + kt * BK;
        uint32_t d = sdst + st * STAGE_BYTES + p * PLANE_BYTES;
        CP_ASYNC16(d, s0);
        CP_ASYNC16(d + 64 * ROWB, s0 + (size_t)64 * NDIM);
    }
}

__global__ void __launch_bounds__(256, 2)
gemm_kernel(const bf16* __restrict__ Ah, const bf16* __restrict__ Al,
            const bf16* __restrict__ Bh, const bf16* __restrict__ Bl,
            float* __restrict__ outF, bf16* __restrict__ outH,
            bf16* __restrict__ outL, int epi) {
    extern __shared__ char smem[];
    const uint32_t sbase = smem_to_u32(smem);
    const int tid = threadIdx.x;
    const int lane = tid & 31;
    const int wid = tid >> 5;
    const int wm = wid & 3;        // 4 warps along M
    const int wn = wid >> 2;       // 2 warps along N
    const int m0 = blockIdx.y * BM;
    const int n0 = blockIdx.x * BN;

    // ---- loader setup: thread covers rows lr and lr+64, 16B chunk lc ----
    const int lr = tid >> 2;       // 0..63
    const int lc = tid & 3;        // 0..3
    const bf16* gsrc[4] = {
        Ah + (size_t)(m0 + lr) * NDIM + lc * 8,
        Al + (size_t)(m0 + lr) * NDIM + lc * 8,
        Bh + (size_t)(n0 + lr) * NDIM + lc * 8,
        Bl + (size_t)(n0 + lr) * NDIM + lc * 8,
    };
    const uint32_t sdst = sbase + lr * ROWB + lc * 16;

    // ---- ldmatrix per-lane base offsets ----
    const uint32_t a_off = (uint32_t)((wm * 32 + (lane & 15)) * ROWB + (lane >> 4) * 16);
    const uint32_t b_off = (uint32_t)((wn * 64 + (lane & 15)) * ROWB + (lane >> 4) * 16);

    float acc[2][8][4];
    #pragma unroll
    for (int a = 0; a < 2; ++a)
        #pragma unroll
        for (int b = 0; b < 8; ++b)
            #pragma unroll
            for (int c = 0; c < 4; ++c) acc[a][b][c] = 0.0f;

    load_stage(gsrc, sdst, 0, 0);
    CP_COMMIT();
    load_stage(gsrc, sdst, 1, 1);
    CP_COMMIT();

    for (int kt = 0; kt < KT; ++kt) {
        CP_WAIT1();
        __syncthreads();

        const uint32_t stg = sbase + (kt & 1) * STAGE_BYTES;
        #pragma unroll
        for (int s = 0; s < 2; ++s) {
            uint32_t ah[2][4], al[2][4];
            #pragma unroll
            for (int mt = 0; mt < 2; ++mt) {
                LDSM4(ah[mt], stg + a_off + mt * (16 * ROWB) + s * 32);
                LDSM4(al[mt], stg + PLANE_BYTES + a_off + mt * (16 * ROWB) + s * 32);
            }
            #pragma unroll
            for (int g = 0; g < 4; ++g) {
                uint32_t bh[4], bl[4];
                LDSM4(bh, stg + 2 * PLANE_BYTES + b_off + g * (16 * ROWB) + s * 32);
                LDSM4(bl, stg + 3 * PLANE_BYTES + b_off + g * (16 * ROWB) + s * 32);
                #pragma unroll
                for (int mt = 0; mt < 2; ++mt) {
                    MMA16816(acc[mt][2 * g],     ah[mt], bh[0], bh[2]);
                    MMA16816(acc[mt][2 * g],     al[mt], bh[0], bh[2]);
                    MMA16816(acc[mt][2 * g],     ah[mt], bl[0], bl[2]);
                    MMA16816(acc[mt][2 * g + 1], ah[mt], bh[1], bh[3]);
                    MMA16816(acc[mt][2 * g + 1], al[mt], bh[1], bh[3]);
                    MMA16816(acc[mt][2 * g + 1], ah[mt], bl[1], bl[3]);
                }
            }
        }

        __syncthreads();
        if (kt + 2 < KT) load_stage(gsrc, sdst, kt & 1, kt + 2);
        CP_COMMIT();
    }

    // ---- epilogue ----
    // acc[mt][nt][c]: row = m0 + wm*32 + mt*16 + (lane>>2) + 8*(c>>1)
    //                 col = n0 + wn*64 + nt*8 + (lane&3)*2 + (c&1)
    const int r0 = m0 + wm * 32 + (lane >> 2);
    const int c0 = n0 + wn * 64 + (lane & 3) * 2;
    if (epi == 0) {
        #pragma unroll
        for (int mt = 0; mt < 2; ++mt)
            #pragma unroll
            for (int nt = 0; nt < 8; ++nt) {
                int row = r0 + mt * 16;
                int col = c0 + nt * 8;
                *(float2*)&outF[(size_t)row * NDIM + col] =
                    make_float2(acc[mt][nt][0], acc[mt][nt][1]);
                *(float2*)&outF[(size_t)(row + 8) * NDIM + col] =
                    make_float2(acc[mt][nt][2], acc[mt][nt][3]);
            }
    } else {
        #pragma unroll
        for (int mt = 0; mt < 2; ++mt)
            #pragma unroll
            for (int nt = 0; nt < 8; ++nt) {
                int row = r0 + mt * 16;
                int col = c0 + nt * 8;
                uint32_t h, l;
                split_pair(acc[mt][nt][0], acc[mt][nt][1], h, l);
                *(uint32_t*)&outH[(size_t)row * NDIM + col] = h;
                *(uint32_t*)&outL[(size_t)row * NDIM + col] = l;
                split_pair(acc[mt][nt][2], acc[mt][nt][3], h, l);
                *(uint32_t*)&outH[(size_t)(row + 8) * NDIM + col] = h;
                *(uint32_t*)&outL[(size_t)(row + 8) * NDIM + col] = l;
            }
    }
}

// ---------------------------------------------------------------------------
extern "C" void kernel_launch(void* const* d_in, const int* in_sizes, int n_in,
                              void* d_out, int out_size) {
    const float* x = (const float*)d_in[0];
    float* out = (float*)d_out;

    bf16 *xh, *xl, *S1h, *S1l, *C0h, *C0l, *Yth, *Ytl;
    cudaGetSymbolAddress((void**)&xh, g_xh);
    cudaGetSymbolAddress((void**)&xl, g_xl);
    cudaGetSymbolAddress((void**)&S1h, g_S1h);
    cudaGetSymbolAddress((void**)&S1l, g_S1l);
    cudaGetSymbolAddress((void**)&C0h, g_C0h);
    cudaGetSymbolAddress((void**)&C0l, g_C0l);
    cudaGetSymbolAddress((void**)&Yth, g_Yth);
    cudaGetSymbolAddress((void**)&Ytl, g_Ytl);

    cudaFuncSetAttribute(gemm_kernel,
                         cudaFuncAttributeMaxDynamicSharedMemorySize, SMEM_BYTES);

    build_table_kernel<<<64, 256>>>();
    gen_basis_kernel<<<(NDIM * 2048) / 256, 256>>>();
    split_x_kernel<<<(NDIM * NDIM / 4) / 256, 256>>>((const float4*)x);

    dim3 grid(NDIM / BN, NDIM / BM);
    // GEMM1: Yt[v,p] = sum_q S1[v,q] * x[p,q]  -> split bf16 epilogue
    gemm_kernel<<<grid, 256, SMEM_BYTES>>>(S1h, S1l, xh, xl,
                                           nullptr, Yth, Ytl, 1);
    // GEMM2: out[u,v] = sum_p C0[u,p] * Yt[v,p] -> fp32 epilogue
    gemm_kernel<<<grid, 256, SMEM_BYTES>>>(C0h, C0l, Yth, Ytl,
                                           out, nullptr, nullptr, 0);
}

// round 4
// speedup vs baseline: 1.9234x; 1.9234x over previous
#include <cuda_runtime.h>
#include <cuda_bf16.h>
#include <cstdint>

// ============================================================================
// IDCST2: out = C0 @ x @ S1^T, M=N=4096 fp32.  Plain-sm_103 tensor path
// (mma.sync m16n8k16 bf16 + ldmatrix + cp.async), 3-term bf16 split.
//
// R3: even/odd mirror fold on both transforms -> half the GEMM MACs.
//   S1[N-1-v,q] = (-1)^(q+1) S1[v,q]:  Ye=S1e@xe^T, Yo=S1o@xo^T (2048x4096x2048)
//       Yt[v]=Ye+Yo, Yt[N-1-v]=Yo-Ye   (combine1, also re-splits to bf16 h/l
//                                        partitioned by parity of p for GEMM2)
//   C0[M-1-u,p] = (-1)^p C0[u,p]:      E=C0e@Yte^T, O=C0o@Yto^T
//       out[u]=E+O, out[M-1-u]=E-O     (combine2)
// All 4 sub-GEMMs share one shape: M=2048, N=4096, K=2048, fp32 epilogue.
// ============================================================================

#define NDIM 4096
#define KDIM 2048
typedef __nv_bfloat16 bf16;

static constexpr int BM = 128;
static constexpr int BN = 128;
static constexpr int BK = 32;
static constexpr int KT = KDIM / BK;       // 64 k-tiles

static constexpr int ROWB        = 80;              // padded smem row stride
static constexpr int PLANE_BYTES = 128 * ROWB;      // 10240
static constexpr int STAGE_BYTES = 4 * PLANE_BYTES; // 40960 (Ah,Al,Bh,Bl)
static constexpr int SMEM_BYTES  = 2 * STAGE_BYTES; // 81920 (double buffer)

// -------------------- device scratch ----------------------------------------
__device__ float g_table[16384];
// x de-interleaved by q parity: [4096 p x 2048 q']
__device__ bf16 g_xe_h[(size_t)NDIM * KDIM];
__device__ bf16 g_xe_l[(size_t)NDIM * KDIM];
__device__ bf16 g_xo_h[(size_t)NDIM * KDIM];
__device__ bf16 g_xo_l[(size_t)NDIM * KDIM];
// folded bases: [2048 x 2048]
__device__ bf16 g_S1e_h[(size_t)KDIM * KDIM];
__device__ bf16 g_S1e_l[(size_t)KDIM * KDIM];
__device__ bf16 g_S1o_h[(size_t)KDIM * KDIM];
__device__ bf16 g_S1o_l[(size_t)KDIM * KDIM];
__device__ bf16 g_C0e_h[(size_t)KDIM * KDIM];
__device__ bf16 g_C0e_l[(size_t)KDIM * KDIM];
__device__ bf16 g_C0o_h[(size_t)KDIM * KDIM];
__device__ bf16 g_C0o_l[(size_t)KDIM * KDIM];
// fp32 GEMM outputs [2048 x 4096]; reused: Ye/Yo then E/O
__device__ float g_P0[(size_t)KDIM * NDIM];
__device__ float g_P1[(size_t)KDIM * NDIM];
// Yt partitioned by p parity, split bf16: [4096 v x 2048 p']
__device__ bf16 g_Yte_h[(size_t)NDIM * KDIM];
__device__ bf16 g_Yte_l[(size_t)NDIM * KDIM];
__device__ bf16 g_Yto_h[(size_t)NDIM * KDIM];
__device__ bf16 g_Yto_l[(size_t)NDIM * KDIM];

// -------------------- helpers ------------------------------------------------
__device__ __forceinline__ uint32_t smem_to_u32(const void* p) {
    uint32_t a;
    asm("{ .reg .u64 t; cvta.to.shared.u64 t, %1; cvt.u32.u64 %0, t; }" : "=r"(a) : "l"(p));
    return a;
}

__device__ __forceinline__ void split_pair(float x, float y, uint32_t& h, uint32_t& l) {
    __nv_bfloat162 H = __floats2bfloat162_rn(x, y);
    float2 F = __bfloat1622float2(H);
    __nv_bfloat162 L = __floats2bfloat162_rn(x - F.x, y - F.y);
    h = *(uint32_t*)&H;
    l = *(uint32_t*)&L;
}

#define CP_ASYNC16(dst, src) \
    asm volatile("cp.async.cg.shared.global [%0], [%1], 16;" :: "r"(dst), "l"(src))
#define CP_COMMIT() asm volatile("cp.async.commit_group;" ::: "memory")
#define CP_WAIT1()  asm volatile("cp.async.wait_group 1;"  ::: "memory")

#define LDSM4(r, addr) \
    asm volatile("ldmatrix.sync.aligned.m8n8.x4.shared.b16 {%0,%1,%2,%3}, [%4];" \
                 : "=r"((r)[0]), "=r"((r)[1]), "=r"((r)[2]), "=r"((r)[3]) : "r"(addr))

#define MMA16816(d, a, b0, b1) \
    asm volatile("mma.sync.aligned.m16n8k16.row.col.f32.bf16.bf16.f32 " \
                 "{%0,%1,%2,%3}, {%4,%5,%6,%7}, {%8,%9}, {%0,%1,%2,%3};" \
                 : "+f"((d)[0]), "+f"((d)[1]), "+f"((d)[2]), "+f"((d)[3]) \
                 : "r"((a)[0]), "r"((a)[1]), "r"((a)[2]), "r"((a)[3]), "r"(b0), "r"(b1))

// ---------------------------------------------------------------------------
// sin table: g_table[r] = sin(pi * r / 8192), r in [0, 16384)
// ---------------------------------------------------------------------------
__global__ void build_table_kernel() {
    int r = blockIdx.x * 256 + threadIdx.x;
    float s, c;
    sincospif((float)r * (1.0f / 8192.0f), &s, &c);
    g_table[r] = s;
}

// folded bases: i in [0,2048) row, pair of cols j2,j2+1.
// S1e[i,q']=sin(pi(2i+1)(2q')/8192); S1o: 2q'+1. C0e/C0o: cos via +4096.
__global__ void gen_basis_kernel() {
    int t = blockIdx.x * 256 + threadIdx.x;   // 2048*1024 threads
    int i = t >> 10;
    int j2 = (t & 1023) << 1;
    int step = 2 * i + 1;
    int aE0 = (step * (j2 << 1)) & 16383;
    int aE1 = (aE0 + 2 * step) & 16383;
    int aO0 = (aE0 + step) & 16383;
    int aO1 = (aO0 + 2 * step) & 16383;
    float sE0 = g_table[aE0], sE1 = g_table[aE1];
    float sO0 = g_table[aO0], sO1 = g_table[aO1];
    float cE0 = g_table[(aE0 + 4096) & 16383], cE1 = g_table[(aE1 + 4096) & 16383];
    float cO0 = g_table[(aO0 + 4096) & 16383], cO1 = g_table[(aO1 + 4096) & 16383];
    size_t off = ((size_t)i << 11) + j2;
    uint32_t h, l;
    split_pair(sE0, sE1, h, l);
    *(uint32_t*)(g_S1e_h + off) = h; *(uint32_t*)(g_S1e_l + off) = l;
    split_pair(sO0, sO1, h, l);
    *(uint32_t*)(g_S1o_h + off) = h; *(uint32_t*)(g_S1o_l + off) = l;
    split_pair(cE0, cE1, h, l);
    *(uint32_t*)(g_C0e_h + off) = h; *(uint32_t*)(g_C0e_l + off) = l;
    split_pair(cO0, cO1, h, l);
    *(uint32_t*)(g_C0o_h + off) = h; *(uint32_t*)(g_C0o_l + off) = l;
}

// de-interleave x by column parity + bf16 split. thread = one float4 (4 q).
__global__ void split_x_kernel(const float4* __restrict__ x) {
    int t = blockIdx.x * 256 + threadIdx.x;   // 4096*1024 threads
    int p = t >> 10;
    int j = t & 1023;                          // q = 4j..4j+3 -> q' = 2j,2j+1
    float4 v = x[t];
    size_t off = ((size_t)p << 11) + (j << 1);
    uint32_t h, l;
    split_pair(v.x, v.z, h, l);                // even q
    *(uint32_t*)(g_xe_h + off) = h; *(uint32_t*)(g_xe_l + off) = l;
    split_pair(v.y, v.w, h, l);                // odd q
    *(uint32_t*)(g_xo_h + off) = h; *(uint32_t*)(g_xo_l + off) = l;
}

// combine1: Yt[v]=Ye+Yo, Yt[4095-v]=Yo-Ye; partition by p parity; bf16 split.
__global__ void combine1_kernel() {
    int t = blockIdx.x * 256 + threadIdx.x;   // 2048*1024 threads
    int v = t >> 10;
    int j = t & 1023;                          // p = 4j..4j+3 -> p' = 2j,2j+1
    float4 e = *(const float4*)(g_P0 + ((size_t)v << 12) + (j << 2));
    float4 o = *(const float4*)(g_P1 + ((size_t)v << 12) + (j << 2));
    float4 s = make_float4(e.x + o.x, e.y + o.y, e.z + o.z, e.w + o.w);
    float4 d = make_float4(o.x - e.x, o.y - e.y, o.z - e.z, o.w - e.w);
    size_t offA = ((size_t)v << 11) + (j << 1);
    size_t offB = ((size_t)(NDIM - 1 - v) << 11) + (j << 1);
    uint32_t h, l;
    split_pair(s.x, s.z, h, l);   // even p -> Yte row v
    *(uint32_t*)(g_Yte_h + offA) = h; *(uint32_t*)(g_Yte_l + offA) = l;
    split_pair(s.y, s.w, h, l);   // odd p -> Yto row v
    *(uint32_t*)(g_Yto_h + offA) = h; *(uint32_t*)(g_Yto_l + offA) = l;
    split_pair(d.x, d.z, h, l);   // even p -> Yte row 4095-v
    *(uint32_t*)(g_Yte_h + offB) = h; *(uint32_t*)(g_Yte_l + offB) = l;
    split_pair(d.y, d.w, h, l);   // odd p -> Yto row 4095-v
    *(uint32_t*)(g_Yto_h + offB) = h; *(uint32_t*)(g_Yto_l + offB) = l;
}

// combine2: out[u]=E+O, out[4095-u]=E-O.
__global__ void combine2_kernel(float* __restrict__ out) {
    int t = blockIdx.x * 256 + threadIdx.x;   // 2048*1024 threads
    int u = t >> 10;
    int j = t & 1023;
    float4 e = *(const float4*)(g_P0 + ((size_t)u << 12) + (j << 2));
    float4 o = *(const float4*)(g_P1 + ((size_t)u << 12) + (j << 2));
    *(float4*)(out + ((size_t)u << 12) + (j << 2)) =
        make_float4(e.x + o.x, e.y + o.y, e.z + o.z, e.w + o.w);
    *(float4*)(out + ((size_t)(NDIM - 1 - u) << 12) + (j << 2)) =
        make_float4(e.x - o.x, e.y - o.y, e.z - o.z, e.w - o.w);
}

// ---------------------------------------------------------------------------
// GEMM: D[m,n] = sum_k A[m,k]*B[n,k]; M=2048, N=4096, K=2048; bf16 split x3.
// blockIdx.z selects operand set 0/1. fp32 row-major store (ld=4096).
// ---------------------------------------------------------------------------
__device__ __forceinline__ void load_stage(const bf16* const (&gsrc)[4],
                                           uint32_t sdst, int st, int kt) {
    #pragma unroll
    for (int p = 0; p < 4; ++p) {
        const bf16* s0 = gsrc[p] + kt * BK;
        uint32_t d = sdst + st * STAGE_BYTES + p * PLANE_BYTES;
        CP_ASYNC16(d, s0);
        CP_ASYNC16(d + 64 * ROWB, s0 + (size_t)64 * KDIM);
    }
}

__global__ void __launch_bounds__(256, 2)
gemm_kernel(const bf16* __restrict__ Ah0, const bf16* __restrict__ Al0,
            const bf16* __restrict__ Bh0, const bf16* __restrict__ Bl0,
            float* __restrict__ D0,
            const bf16* __restrict__ Ah1, const bf16* __restrict__ Al1,
            const bf16* __restrict__ Bh1, const bf16* __restrict__ Bl1,
            float* __restrict__ D1) {
    extern __shared__ char smem[];
    const uint32_t sbase = smem_to_u32(smem);
    const int tid = threadIdx.x;
    const int lane = tid & 31;
    const int wid = tid >> 5;
    const int wm = wid & 3;
    const int wn = wid >> 2;
    const int m0 = blockIdx.y * BM;
    const int n0 = blockIdx.x * BN;
    const int z = blockIdx.z;

    const bf16* Ah = z ? Ah1 : Ah0;
    const bf16* Al = z ? Al1 : Al0;
    const bf16* Bh = z ? Bh1 : Bh0;
    const bf16* Bl = z ? Bl1 : Bl0;
    float* D = z ? D1 : D0;

    const int lr = tid >> 2;
    const int lc = tid & 3;
    const bf16* gsrc[4] = {
        Ah + (size_t)(m0 + lr) * KDIM + lc * 8,
        Al + (size_t)(m0 + lr) * KDIM + lc * 8,
        Bh + (size_t)(n0 + lr) * KDIM + lc * 8,
        Bl + (size_t)(n0 + lr) * KDIM + lc * 8,
    };
    const uint32_t sdst = sbase + lr * ROWB + lc * 16;

    const uint32_t a_off = (uint32_t)((wm * 32 + (lane & 15)) * ROWB + (lane >> 4) * 16);
    const uint32_t b_off = (uint32_t)((wn * 64 + (lane & 15)) * ROWB + (lane >> 4) * 16);

    float acc[2][8][4];
    #pragma unroll
    for (int a = 0; a < 2; ++a)
        #pragma unroll
        for (int b = 0; b < 8; ++b)
            #pragma unroll
            for (int c = 0; c < 4; ++c) acc[a][b][c] = 0.0f;

    load_stage(gsrc, sdst, 0, 0);
    CP_COMMIT();
    load_stage(gsrc, sdst, 1, 1);
    CP_COMMIT();

    for (int kt = 0; kt < KT; ++kt) {
        CP_WAIT1();
        __syncthreads();

        const uint32_t stg = sbase + (kt & 1) * STAGE_BYTES;
        #pragma unroll
        for (int s = 0; s < 2; ++s) {
            uint32_t ah[2][4], al[2][4];
            #pragma unroll
            for (int mt = 0; mt < 2; ++mt) {
                LDSM4(ah[mt], stg + a_off + mt * (16 * ROWB) + s * 32);
                LDSM4(al[mt], stg + PLANE_BYTES + a_off + mt * (16 * ROWB) + s * 32);
            }
            #pragma unroll
            for (int g = 0; g < 4; ++g) {
                uint32_t bh[4], bl[4];
                LDSM4(bh, stg + 2 * PLANE_BYTES + b_off + g * (16 * ROWB) + s * 32);
                LDSM4(bl, stg + 3 * PLANE_BYTES + b_off + g * (16 * ROWB) + s * 32);
                #pragma unroll
                for (int mt = 0; mt < 2; ++mt) {
                    MMA16816(acc[mt][2 * g],     ah[mt], bh[0], bh[2]);
                    MMA16816(acc[mt][2 * g],     al[mt], bh[0], bh[2]);
                    MMA16816(acc[mt][2 * g],     ah[mt], bl[0], bl[2]);
                    MMA16816(acc[mt][2 * g + 1], ah[mt], bh[1], bh[3]);
                    MMA16816(acc[mt][2 * g + 1], al[mt], bh[1], bh[3]);
                    MMA16816(acc[mt][2 * g + 1], ah[mt], bl[1], bl[3]);
                }
            }
        }

        __syncthreads();
        if (kt + 2 < KT) load_stage(gsrc, sdst, kt & 1, kt + 2);
        CP_COMMIT();
    }

    // epilogue: fp32 row-major, D is [2048 x 4096]
    const int r0 = m0 + wm * 32 + (lane >> 2);
    const int c0 = n0 + wn * 64 + (lane & 3) * 2;
    #pragma unroll
    for (int mt = 0; mt < 2; ++mt)
        #pragma unroll
        for (int nt = 0; nt < 8; ++nt) {
            int row = r0 + mt * 16;
            int col = c0 + nt * 8;
            *(float2*)&D[(size_t)row * NDIM + col] =
                make_float2(acc[mt][nt][0], acc[mt][nt][1]);
            *(float2*)&D[(size_t)(row + 8) * NDIM + col] =
                make_float2(acc[mt][nt][2], acc[mt][nt][3]);
        }
}

// ---------------------------------------------------------------------------
extern "C" void kernel_launch(void* const* d_in, const int* in_sizes, int n_in,
                              void* d_out, int out_size) {
    const float* x = (const float*)d_in[0];
    float* out = (float*)d_out;

    bf16 *xe_h, *xe_l, *xo_h, *xo_l;
    bf16 *S1e_h, *S1e_l, *S1o_h, *S1o_l, *C0e_h, *C0e_l, *C0o_h, *C0o_l;
    bf16 *Yte_h, *Yte_l, *Yto_h, *Yto_l;
    float *P0, *P1;
    cudaGetSymbolAddress((void**)&xe_h, g_xe_h);
    cudaGetSymbolAddress((void**)&xe_l, g_xe_l);
    cudaGetSymbolAddress((void**)&xo_h, g_xo_h);
    cudaGetSymbolAddress((void**)&xo_l, g_xo_l);
    cudaGetSymbolAddress((void**)&S1e_h, g_S1e_h);
    cudaGetSymbolAddress((void**)&S1e_l, g_S1e_l);
    cudaGetSymbolAddress((void**)&S1o_h, g_S1o_h);
    cudaGetSymbolAddress((void**)&S1o_l, g_S1o_l);
    cudaGetSymbolAddress((void**)&C0e_h, g_C0e_h);
    cudaGetSymbolAddress((void**)&C0e_l, g_C0e_l);
    cudaGetSymbolAddress((void**)&C0o_h, g_C0o_h);
    cudaGetSymbolAddress((void**)&C0o_l, g_C0o_l);
    cudaGetSymbolAddress((void**)&Yte_h, g_Yte_h);
    cudaGetSymbolAddress((void**)&Yte_l, g_Yte_l);
    cudaGetSymbolAddress((void**)&Yto_h, g_Yto_h);
    cudaGetSymbolAddress((void**)&Yto_l, g_Yto_l);
    cudaGetSymbolAddress((void**)&P0, g_P0);
    cudaGetSymbolAddress((void**)&P1, g_P1);

    cudaFuncSetAttribute(gemm_kernel,
                         cudaFuncAttributeMaxDynamicSharedMemorySize, SMEM_BYTES);

    build_table_kernel<<<64, 256>>>();
    gen_basis_kernel<<<(KDIM * 1024) / 256, 256>>>();
    split_x_kernel<<<(NDIM * 1024) / 256, 256>>>((const float4*)x);

    dim3 grid(NDIM / BN, KDIM / BM, 2);   // 32 x 16 x 2
    // Stage 1: Ye = S1e @ xe^T (z=0), Yo = S1o @ xo^T (z=1)
    gemm_kernel<<<grid, 256, SMEM_BYTES>>>(S1e_h, S1e_l, xe_h, xe_l, P0,
                                           S1o_h, S1o_l, xo_h, xo_l, P1);
    combine1_kernel<<<(KDIM * 1024) / 256, 256>>>();
    // Stage 2: E = C0e @ Yte^T (z=0), O = C0o @ Yto^T (z=1)
    gemm_kernel<<<grid, 256, SMEM_BYTES>>>(C0e_h, C0e_l, Yte_h, Yte_l, P0,
                                           C0o_h, C0o_l, Yto_h, Yto_l, P1);
    combine2_kernel<<<(KDIM * 1024) / 256, 256>>>(out);
}

// round 6
// speedup vs baseline: 2.2099x; 1.1489x over previous
#include <cuda_runtime.h>
#include <cuda_bf16.h>
#include <cstdint>

// ============================================================================
// IDCST2: out = C0 @ x @ S1^T, M=N=4096 fp32.  Plain-sm_103 tensor path
// (mma.sync m16n8k16 bf16 + ldmatrix + cp.async), 3-term bf16 split,
// even/odd mirror fold (R3).
// R5: 3-stage cp.async pipeline, ONE __syncthreads per k-tile, pad-free smem
// with CORRECT 64B-row swizzle: chunk ^= (row>>1)&3  (2-bit, in-row, proven
// conflict-free for both cp.async writes and ldmatrix reads).
// ============================================================================

#define NDIM 4096
#define KDIM 2048
typedef __nv_bfloat16 bf16;

static constexpr int BM = 128;
static constexpr int BN = 128;
static constexpr int BK = 32;
static constexpr int KT = KDIM / BK;       // 64 k-tiles

static constexpr int ROWB        = 64;              // exact 64B rows (swizzled)
static constexpr int PLANE_BYTES = 128 * ROWB;      // 8192
static constexpr int STAGE_BYTES = 4 * PLANE_BYTES; // 32768 (Ah,Al,Bh,Bl)
static constexpr int NSTAGE      = 3;
static constexpr int SMEM_BYTES  = NSTAGE * STAGE_BYTES; // 98304

// -------------------- device scratch ----------------------------------------
__device__ float g_table[16384];
__device__ bf16 g_xe_h[(size_t)NDIM * KDIM];
__device__ bf16 g_xe_l[(size_t)NDIM * KDIM];
__device__ bf16 g_xo_h[(size_t)NDIM * KDIM];
__device__ bf16 g_xo_l[(size_t)NDIM * KDIM];
__device__ bf16 g_S1e_h[(size_t)KDIM * KDIM];
__device__ bf16 g_S1e_l[(size_t)KDIM * KDIM];
__device__ bf16 g_S1o_h[(size_t)KDIM * KDIM];
__device__ bf16 g_S1o_l[(size_t)KDIM * KDIM];
__device__ bf16 g_C0e_h[(size_t)KDIM * KDIM];
__device__ bf16 g_C0e_l[(size_t)KDIM * KDIM];
__device__ bf16 g_C0o_h[(size_t)KDIM * KDIM];
__device__ bf16 g_C0o_l[(size_t)KDIM * KDIM];
__device__ float g_P0[(size_t)KDIM * NDIM];
__device__ float g_P1[(size_t)KDIM * NDIM];
__device__ bf16 g_Yte_h[(size_t)NDIM * KDIM];
__device__ bf16 g_Yte_l[(size_t)NDIM * KDIM];
__device__ bf16 g_Yto_h[(size_t)NDIM * KDIM];
__device__ bf16 g_Yto_l[(size_t)NDIM * KDIM];

// -------------------- helpers ------------------------------------------------
__device__ __forceinline__ uint32_t smem_to_u32(const void* p) {
    uint32_t a;
    asm("{ .reg .u64 t; cvta.to.shared.u64 t, %1; cvt.u32.u64 %0, t; }" : "=r"(a) : "l"(p));
    return a;
}

__device__ __forceinline__ void split_pair(float x, float y, uint32_t& h, uint32_t& l) {
    __nv_bfloat162 H = __floats2bfloat162_rn(x, y);
    float2 F = __bfloat1622float2(H);
    __nv_bfloat162 L = __floats2bfloat162_rn(x - F.x, y - F.y);
    h = *(uint32_t*)&H;
    l = *(uint32_t*)&L;
}

#define CP_ASYNC16(dst, src) \
    asm volatile("cp.async.cg.shared.global [%0], [%1], 16;" :: "r"(dst), "l"(src))
#define CP_COMMIT() asm volatile("cp.async.commit_group;" ::: "memory")
#define CP_WAIT1()  asm volatile("cp.async.wait_group 1;"  ::: "memory")

#define LDSM4(r, addr) \
    asm volatile("ldmatrix.sync.aligned.m8n8.x4.shared.b16 {%0,%1,%2,%3}, [%4];" \
                 : "=r"((r)[0]), "=r"((r)[1]), "=r"((r)[2]), "=r"((r)[3]) : "r"(addr))

#define MMA16816(d, a, b0, b1) \
    asm volatile("mma.sync.aligned.m16n8k16.row.col.f32.bf16.bf16.f32 " \
                 "{%0,%1,%2,%3}, {%4,%5,%6,%7}, {%8,%9}, {%0,%1,%2,%3};" \
                 : "+f"((d)[0]), "+f"((d)[1]), "+f"((d)[2]), "+f"((d)[3]) \
                 : "r"((a)[0]), "r"((a)[1]), "r"((a)[2]), "r"((a)[3]), "r"(b0), "r"(b1))

// ---------------------------------------------------------------------------
__global__ void build_table_kernel() {
    int r = blockIdx.x * 256 + threadIdx.x;
    float s, c;
    sincospif((float)r * (1.0f / 8192.0f), &s, &c);
    g_table[r] = s;
}

__global__ void gen_basis_kernel() {
    int t = blockIdx.x * 256 + threadIdx.x;   // 2048*1024 threads
    int i = t >> 10;
    int j2 = (t & 1023) << 1;
    int step = 2 * i + 1;
    int aE0 = (step * (j2 << 1)) & 16383;
    int aE1 = (aE0 + 2 * step) & 16383;
    int aO0 = (aE0 + step) & 16383;
    int aO1 = (aO0 + 2 * step) & 16383;
    float sE0 = g_table[aE0], sE1 = g_table[aE1];
    float sO0 = g_table[aO0], sO1 = g_table[aO1];
    float cE0 = g_table[(aE0 + 4096) & 16383], cE1 = g_table[(aE1 + 4096) & 16383];
    float cO0 = g_table[(aO0 + 4096) & 16383], cO1 = g_table[(aO1 + 4096) & 16383];
    size_t off = ((size_t)i << 11) + j2;
    uint32_t h, l;
    split_pair(sE0, sE1, h, l);
    *(uint32_t*)(g_S1e_h + off) = h; *(uint32_t*)(g_S1e_l + off) = l;
    split_pair(sO0, sO1, h, l);
    *(uint32_t*)(g_S1o_h + off) = h; *(uint32_t*)(g_S1o_l + off) = l;
    split_pair(cE0, cE1, h, l);
    *(uint32_t*)(g_C0e_h + off) = h; *(uint32_t*)(g_C0e_l + off) = l;
    split_pair(cO0, cO1, h, l);
    *(uint32_t*)(g_C0o_h + off) = h; *(uint32_t*)(g_C0o_l + off) = l;
}

__global__ void split_x_kernel(const float4* __restrict__ x) {
    int t = blockIdx.x * 256 + threadIdx.x;   // 4096*1024 threads
    int p = t >> 10;
    int j = t & 1023;
    float4 v = x[t];
    size_t off = ((size_t)p << 11) + (j << 1);
    uint32_t h, l;
    split_pair(v.x, v.z, h, l);
    *(uint32_t*)(g_xe_h + off) = h; *(uint32_t*)(g_xe_l + off) = l;
    split_pair(v.y, v.w, h, l);
    *(uint32_t*)(g_xo_h + off) = h; *(uint32_t*)(g_xo_l + off) = l;
}

__global__ void combine1_kernel() {
    int t = blockIdx.x * 256 + threadIdx.x;   // 2048*1024 threads
    int v = t >> 10;
    int j = t & 1023;
    float4 e = *(const float4*)(g_P0 + ((size_t)v << 12) + (j << 2));
    float4 o = *(const float4*)(g_P1 + ((size_t)v << 12) + (j << 2));
    float4 s = make_float4(e.x + o.x, e.y + o.y, e.z + o.z, e.w + o.w);
    float4 d = make_float4(o.x - e.x, o.y - e.y, o.z - e.z, o.w - e.w);
    size_t offA = ((size_t)v << 11) + (j << 1);
    size_t offB = ((size_t)(NDIM - 1 - v) << 11) + (j << 1);
    uint32_t h, l;
    split_pair(s.x, s.z, h, l);
    *(uint32_t*)(g_Yte_h + offA) = h; *(uint32_t*)(g_Yte_l + offA) = l;
    split_pair(s.y, s.w, h, l);
    *(uint32_t*)(g_Yto_h + offA) = h; *(uint32_t*)(g_Yto_l + offA) = l;
    split_pair(d.x, d.z, h, l);
    *(uint32_t*)(g_Yte_h + offB) = h; *(uint32_t*)(g_Yte_l + offB) = l;
    split_pair(d.y, d.w, h, l);
    *(uint32_t*)(g_Yto_h + offB) = h; *(uint32_t*)(g_Yto_l + offB) = l;
}

__global__ void combine2_kernel(float* __restrict__ out) {
    int t = blockIdx.x * 256 + threadIdx.x;   // 2048*1024 threads
    int u = t >> 10;
    int j = t & 1023;
    float4 e = *(const float4*)(g_P0 + ((size_t)u << 12) + (j << 2));
    float4 o = *(const float4*)(g_P1 + ((size_t)u << 12) + (j << 2));
    *(float4*)(out + ((size_t)u << 12) + (j << 2)) =
        make_float4(e.x + o.x, e.y + o.y, e.z + o.z, e.w + o.w);
    *(float4*)(out + ((size_t)(NDIM - 1 - u) << 12) + (j << 2)) =
        make_float4(e.x - o.x, e.y - o.y, e.z - o.z, e.w - o.w);
}

// ---------------------------------------------------------------------------
// GEMM: D[m,n] = sum_k A[m,k]*B[n,k]; M=2048, N=4096, K=2048; bf16 split x3.
// 3-stage cp.async pipeline, one sync per k-tile.
// smem swizzle (64B rows, 4x16B chunks): chunk ^= (row>>1)&3.
// ---------------------------------------------------------------------------
__device__ __forceinline__ void load_stage(const bf16* const (&gsrc)[4],
                                           uint32_t sdst, int stage, int kt) {
    #pragma unroll
    for (int p = 0; p < 4; ++p) {
        const bf16* s0 = gsrc[p] + kt * BK;
        uint32_t d = sdst + stage * STAGE_BYTES + p * PLANE_BYTES;
        CP_ASYNC16(d, s0);
        CP_ASYNC16(d + 64 * ROWB, s0 + (size_t)64 * KDIM);
    }
}

__global__ void __launch_bounds__(256, 2)
gemm_kernel(const bf16* __restrict__ Ah0, const bf16* __restrict__ Al0,
            const bf16* __restrict__ Bh0, const bf16* __restrict__ Bl0,
            float* __restrict__ D0,
            const bf16* __restrict__ Ah1, const bf16* __restrict__ Al1,
            const bf16* __restrict__ Bh1, const bf16* __restrict__ Bl1,
            float* __restrict__ D1) {
    extern __shared__ char smem[];
    const uint32_t sbase = smem_to_u32(smem);
    const int tid = threadIdx.x;
    const int lane = tid & 31;
    const int wid = tid >> 5;
    const int wm = wid & 3;
    const int wn = wid >> 2;
    const int m0 = blockIdx.y * BM;
    const int n0 = blockIdx.x * BN;
    const int z = blockIdx.z;

    const bf16* Ah = z ? Ah1 : Ah0;
    const bf16* Al = z ? Al1 : Al0;
    const bf16* Bh = z ? Bh1 : Bh0;
    const bf16* Bl = z ? Bl1 : Bl0;
    float* D = z ? D1 : D0;

    // ---- loader: thread covers rows lr, lr+64; 16B chunk lc (swizzled) ----
    const int lr = tid >> 2;
    const int lc = tid & 3;
    const bf16* gsrc[4] = {
        Ah + (size_t)(m0 + lr) * KDIM + lc * 8,
        Al + (size_t)(m0 + lr) * KDIM + lc * 8,
        Bh + (size_t)(n0 + lr) * KDIM + lc * 8,
        Bl + (size_t)(n0 + lr) * KDIM + lc * 8,
    };
    // swizzled chunk: lc ^ ((lr>>1)&3); same for row lr and lr+64 (bit6 drop)
    const uint32_t sdst =
        sbase + lr * ROWB + (uint32_t)((lc ^ ((lr >> 1) & 3)) << 4);

    // ---- ldmatrix lane addressing (swizzled) ----
    // row = base + (lane&15); base mult of 16 -> mask depends on lane only
    const uint32_t lmask = (uint32_t)(((lane & 15) >> 1) & 3);
    const uint32_t soff0 = (uint32_t)(((lane >> 4) ^ lmask) << 4);
    const uint32_t soff1 = (uint32_t)(((2 + (lane >> 4)) ^ lmask) << 4);
    const uint32_t a_row = (uint32_t)((wm * 32 + (lane & 15)) * ROWB);
    const uint32_t b_row = (uint32_t)((wn * 64 + (lane & 15)) * ROWB);

    float acc[2][8][4];
    #pragma unroll
    for (int a = 0; a < 2; ++a)
        #pragma unroll
        for (int b = 0; b < 8; ++b)
            #pragma unroll
            for (int c = 0; c < 4; ++c) acc[a][b][c] = 0.0f;

    load_stage(gsrc, sdst, 0, 0);
    CP_COMMIT();
    load_stage(gsrc, sdst, 1, 1);
    CP_COMMIT();

    int cs = 0;   // compute stage
    int ls = 2;   // load stage (for kt+2)
    for (int kt = 0; kt < KT; ++kt) {
        CP_WAIT1();
        __syncthreads();

        // prefetch kt+2 into stage computed at kt-1 (safe after the sync)
        if (kt + 2 < KT) load_stage(gsrc, sdst, ls, kt + 2);
        CP_COMMIT();

        const uint32_t stg = sbase + cs * STAGE_BYTES;
        #pragma unroll
        for (int s = 0; s < 2; ++s) {
            const uint32_t soff = s ? soff1 : soff0;
            uint32_t ah[2][4], al[2][4];
            #pragma unroll
            for (int mt = 0; mt < 2; ++mt) {
                LDSM4(ah[mt], stg + a_row + mt * 1024 + soff);
                LDSM4(al[mt], stg + PLANE_BYTES + a_row + mt * 1024 + soff);
            }
            #pragma unroll
            for (int g = 0; g < 4; ++g) {
                uint32_t bh[4], bl[4];
                LDSM4(bh, stg + 2 * PLANE_BYTES + b_row + g * 1024 + soff);
                LDSM4(bl, stg + 3 * PLANE_BYTES + b_row + g * 1024 + soff);
                // interleaved ordering: chain spacing 4 on each accumulator
                MMA16816(acc[0][2 * g],     ah[0], bh[0], bh[2]);
                MMA16816(acc[1][2 * g],     ah[1], bh[0], bh[2]);
                MMA16816(acc[0][2 * g + 1], ah[0], bh[1], bh[3]);
                MMA16816(acc[1][2 * g + 1], ah[1], bh[1], bh[3]);
                MMA16816(acc[0][2 * g],     al[0], bh[0], bh[2]);
                MMA16816(acc[1][2 * g],     al[1], bh[0], bh[2]);
                MMA16816(acc[0][2 * g + 1], al[0], bh[1], bh[3]);
                MMA16816(acc[1][2 * g + 1], al[1], bh[1], bh[3]);
                MMA16816(acc[0][2 * g],     ah[0], bl[0], bl[2]);
                MMA16816(acc[1][2 * g],     ah[1], bl[0], bl[2]);
                MMA16816(acc[0][2 * g + 1], ah[0], bl[1], bl[3]);
                MMA16816(acc[1][2 * g + 1], ah[1], bl[1], bl[3]);
            }
        }

        cs = (cs == 2) ? 0 : cs + 1;
        ls = (ls == 2) ? 0 : ls + 1;
    }

    // ---- epilogue: fp32 row-major, D is [2048 x 4096] ----
    const int r0 = m0 + wm * 32 + (lane >> 2);
    const int c0 = n0 + wn * 64 + (lane & 3) * 2;
    #pragma unroll
    for (int mt = 0; mt < 2; ++mt)
        #pragma unroll
        for (int nt = 0; nt < 8; ++nt) {
            int row = r0 + mt * 16;
            int col = c0 + nt * 8;
            *(float2*)&D[(size_t)row * NDIM + col] =
                make_float2(acc[mt][nt][0], acc[mt][nt][1]);
            *(float2*)&D[(size_t)(row + 8) * NDIM + col] =
                make_float2(acc[mt][nt][2], acc[mt][nt][3]);
        }
}

// ---------------------------------------------------------------------------
extern "C" void kernel_launch(void* const* d_in, const int* in_sizes, int n_in,
                              void* d_out, int out_size) {
    const float* x = (const float*)d_in[0];
    float* out = (float*)d_out;

    bf16 *xe_h, *xe_l, *xo_h, *xo_l;
    bf16 *S1e_h, *S1e_l, *S1o_h, *S1o_l, *C0e_h, *C0e_l, *C0o_h, *C0o_l;
    bf16 *Yte_h, *Yte_l, *Yto_h, *Yto_l;
    float *P0, *P1;
    cudaGetSymbolAddress((void**)&xe_h, g_xe_h);
    cudaGetSymbolAddress((void**)&xe_l, g_xe_l);
    cudaGetSymbolAddress((void**)&xo_h, g_xo_h);
    cudaGetSymbolAddress((void**)&xo_l, g_xo_l);
    cudaGetSymbolAddress((void**)&S1e_h, g_S1e_h);
    cudaGetSymbolAddress((void**)&S1e_l, g_S1e_l);
    cudaGetSymbolAddress((void**)&S1o_h, g_S1o_h);
    cudaGetSymbolAddress((void**)&S1o_l, g_S1o_l);
    cudaGetSymbolAddress((void**)&C0e_h, g_C0e_h);
    cudaGetSymbolAddress((void**)&C0e_l, g_C0e_l);
    cudaGetSymbolAddress((void**)&C0o_h, g_C0o_h);
    cudaGetSymbolAddress((void**)&C0o_l, g_C0o_l);
    cudaGetSymbolAddress((void**)&Yte_h, g_Yte_h);
    cudaGetSymbolAddress((void**)&Yte_l, g_Yte_l);
    cudaGetSymbolAddress((void**)&Yto_h, g_Yto_h);
    cudaGetSymbolAddress((void**)&Yto_l, g_Yto_l);
    cudaGetSymbolAddress((void**)&P0, g_P0);
    cudaGetSymbolAddress((void**)&P1, g_P1);

    cudaFuncSetAttribute(gemm_kernel,
                         cudaFuncAttributeMaxDynamicSharedMemorySize, SMEM_BYTES);

    build_table_kernel<<<64, 256>>>();
    gen_basis_kernel<<<(KDIM * 1024) / 256, 256>>>();
    split_x_kernel<<<(NDIM * 1024) / 256, 256>>>((const float4*)x);

    dim3 grid(NDIM / BN, KDIM / BM, 2);   // 32 x 16 x 2
    gemm_kernel<<<grid, 256, SMEM_BYTES>>>(S1e_h, S1e_l, xe_h, xe_l, P0,
                                           S1o_h, S1o_l, xo_h, xo_l, P1);
    combine1_kernel<<<(KDIM * 1024) / 256, 256>>>();
    gemm_kernel<<<grid, 256, SMEM_BYTES>>>(C0e_h, C0e_l, Yte_h, Yte_l, P0,
                                           C0o_h, C0o_l, Yto_h, Yto_l, P1);
    combine2_kernel<<<(KDIM * 1024) / 256, 256>>>(out);
}

// round 7
// speedup vs baseline: 3.4487x; 1.5606x over previous
#include <cuda_runtime.h>
#include <cuda_bf16.h>
#include <cstdint>

// ============================================================================
// IDCST2: out = C0 @ x @ S1^T, M=N=4096 fp32.  Plain-sm_103 tensor path
// (mma.sync m16n8k16 bf16 + ldmatrix + cp.async), 3-term bf16 split.
//
// R6: two-level fast transform (Lee's identity):
//   T_4096{f} = parity split -> even: T_2048{f_e}; odd: Lee ->
//       O[v] = r_v*( T_2048{w}[v] + (-1)^v f_o[last] ),  w = pairsum(f_o),
//       r_v = 1/(2 cos(pi(2v+1)/8192));  rows v>=V0 computed by direct dense
//       patch GEMM (r_v blowup control).
//   T_2048 computed by one more parity+mirror fold -> dense 1024-size GEMMs.
//   Same for the cos transform (stage 2), whose Lee boundary term vanishes.
// Main GEMMs: 8 x [1024 x 4096 x 1024] (x3 bf16-split terms) = half of R5.
// ============================================================================

#define NDIM 4096
typedef __nv_bfloat16 bf16;

static constexpr int BM = 128;
static constexpr int BN = 128;
static constexpr int BK = 32;
static constexpr int V0 = 1920;           // patch start row
static constexpr int PR = 128;            // patch rows (2048 - V0)

static constexpr int ROWB        = 64;
static constexpr int PLANE_BYTES = 128 * ROWB;      // 8192
static constexpr int STAGE_BYTES = 4 * PLANE_BYTES; // 32768
static constexpr int SMEM_BYTES  = 3 * STAGE_BYTES; // 98304

// -------------------- device scratch ----------------------------------------
__device__ float g_table[16384];
// operands [4096 x 1024] bf16 h/l  (stage1: xee,xeo,we,wo ; stage2: Ytee,Yteo,wce,wco)
__device__ bf16 g_op0h[(size_t)NDIM * 1024]; __device__ bf16 g_op0l[(size_t)NDIM * 1024];
__device__ bf16 g_op1h[(size_t)NDIM * 1024]; __device__ bf16 g_op1l[(size_t)NDIM * 1024];
__device__ bf16 g_op2h[(size_t)NDIM * 1024]; __device__ bf16 g_op2l[(size_t)NDIM * 1024];
__device__ bf16 g_op3h[(size_t)NDIM * 1024]; __device__ bf16 g_op3l[(size_t)NDIM * 1024];
// big operand [4096 x 2048] bf16 h/l (stage1: xo ; stage2: Yto) for patch GEMM
__device__ bf16 g_bigh[(size_t)NDIM * 2048]; __device__ bf16 g_bigl[(size_t)NDIM * 2048];
__device__ float g_b[NDIM];               // boundary vector (stage 1 only)
// bases [1024 x 1024] bf16 h/l
__device__ bf16 g_Se2h[1024 * 1024]; __device__ bf16 g_Se2l[1024 * 1024];
__device__ bf16 g_So2h[1024 * 1024]; __device__ bf16 g_So2l[1024 * 1024];
__device__ bf16 g_Ce2h[1024 * 1024]; __device__ bf16 g_Ce2l[1024 * 1024];
__device__ bf16 g_Co2h[1024 * 1024]; __device__ bf16 g_Co2l[1024 * 1024];
// patch bases [128 x 2048] bf16 h/l
__device__ bf16 g_SoPh[PR * 2048]; __device__ bf16 g_SoPl[PR * 2048];
__device__ bf16 g_CoPh[PR * 2048]; __device__ bf16 g_CoPl[PR * 2048];
// GEMM outputs [1024 x 4096] fp32
__device__ float g_G0[(size_t)1024 * NDIM];
__device__ float g_G1[(size_t)1024 * NDIM];
__device__ float g_G2[(size_t)1024 * NDIM];
__device__ float g_G3[(size_t)1024 * NDIM];
// inner-combine outputs [2048 x 4096] fp32
__device__ float g_Ebuf[(size_t)2048 * NDIM];
__device__ float g_Zbuf[(size_t)2048 * NDIM];
// patch partials [8 x 128 x 4096] and reduced [128 x 4096]
__device__ float g_patchP[(size_t)8 * PR * NDIM];
__device__ float g_patch[(size_t)PR * NDIM];

// -------------------- helpers ------------------------------------------------
__device__ __forceinline__ uint32_t smem_to_u32(const void* p) {
    uint32_t a;
    asm("{ .reg .u64 t; cvta.to.shared.u64 t, %1; cvt.u32.u64 %0, t; }" : "=r"(a) : "l"(p));
    return a;
}

__device__ __forceinline__ void split_pair(float x, float y, uint32_t& h, uint32_t& l) {
    __nv_bfloat162 H = __floats2bfloat162_rn(x, y);
    float2 F = __bfloat1622float2(H);
    __nv_bfloat162 L = __floats2bfloat162_rn(x - F.x, y - F.y);
    h = *(uint32_t*)&H;
    l = *(uint32_t*)&L;
}

#define CP_ASYNC16(dst, src) \
    asm volatile("cp.async.cg.shared.global [%0], [%1], 16;" :: "r"(dst), "l"(src))
#define CP_COMMIT() asm volatile("cp.async.commit_group;" ::: "memory")
#define CP_WAIT1()  asm volatile("cp.async.wait_group 1;"  ::: "memory")

#define LDSM4(r, addr) \
    asm volatile("ldmatrix.sync.aligned.m8n8.x4.shared.b16 {%0,%1,%2,%3}, [%4];" \
                 : "=r"((r)[0]), "=r"((r)[1]), "=r"((r)[2]), "=r"((r)[3]) : "r"(addr))

#define MMA16816(d, a, b0, b1) \
    asm volatile("mma.sync.aligned.m16n8k16.row.col.f32.bf16.bf16.f32 " \
                 "{%0,%1,%2,%3}, {%4,%5,%6,%7}, {%8,%9}, {%0,%1,%2,%3};" \
                 : "+f"((d)[0]), "+f"((d)[1]), "+f"((d)[2]), "+f"((d)[3]) \
                 : "r"((a)[0]), "r"((a)[1]), "r"((a)[2]), "r"((a)[3]), "r"(b0), "r"(b1))

// ---------------------------------------------------------------------------
// sin table: g_table[r] = sin(pi * r / 8192), r in [0, 16384)
// ---------------------------------------------------------------------------
__global__ void build_table_kernel() {
    int r = blockIdx.x * 256 + threadIdx.x;
    float s, c;
    sincospif((float)r * (1.0f / 8192.0f), &s, &c);
    g_table[r] = s;
}

// inner bases:
// Se2[i,q]=sin(pi(2i+1)q/2048)       r = 4(2i+1)q
// So2[i,q]=sin(pi(2i+1)(2q+1)/4096)  r = 2(2i+1)(2q+1)
// Ce2/Co2 = cos versions (phase + 4096)
__global__ void gen_basis_inner() {
    int t = blockIdx.x * 256 + threadIdx.x;   // 1024*512 threads
    int i = t >> 9;
    int j2 = (t & 511) << 1;
    int step = 4 * (2 * i + 1);
    int a0 = ((2 * i + 1) * 4 * j2) & 16383;
    int a1 = (a0 + step) & 16383;
    int b0 = (2 * (2 * i + 1) * (2 * j2 + 1)) & 16383;
    int b1 = (b0 + step) & 16383;
    size_t off = ((size_t)i << 10) + j2;
    uint32_t h, l;
    split_pair(g_table[a0], g_table[a1], h, l);
    *(uint32_t*)(g_Se2h + off) = h; *(uint32_t*)(g_Se2l + off) = l;
    split_pair(g_table[b0], g_table[b1], h, l);
    *(uint32_t*)(g_So2h + off) = h; *(uint32_t*)(g_So2l + off) = l;
    split_pair(g_table[(a0 + 4096) & 16383], g_table[(a1 + 4096) & 16383], h, l);
    *(uint32_t*)(g_Ce2h + off) = h; *(uint32_t*)(g_Ce2l + off) = l;
    split_pair(g_table[(b0 + 4096) & 16383], g_table[(b1 + 4096) & 16383], h, l);
    *(uint32_t*)(g_Co2h + off) = h; *(uint32_t*)(g_Co2l + off) = l;
}

// patch bases: SoP[i,q] = sin(pi(2(V0+i)+1)(2q+1)/8192), CoP = cos version
__global__ void gen_basis_patch() {
    int t = blockIdx.x * 256 + threadIdx.x;   // 128*1024 threads
    int i = t >> 10;
    int j2 = (t & 1023) << 1;
    int M = 2 * (V0 + i) + 1;
    int a0 = (M * (2 * j2 + 1)) & 16383;
    int a1 = (a0 + 2 * M) & 16383;
    size_t off = ((size_t)i << 11) + j2;
    uint32_t h, l;
    split_pair(g_table[a0], g_table[a1], h, l);
    *(uint32_t*)(g_SoPh + off) = h; *(uint32_t*)(g_SoPl + off) = l;
    split_pair(g_table[(a0 + 4096) & 16383], g_table[(a1 + 4096) & 16383], h, l);
    *(uint32_t*)(g_CoPh + off) = h; *(uint32_t*)(g_CoPl + off) = l;
}

// ---------------------------------------------------------------------------
// split_x2: per row p, q-block [16j,16j+16):
//   xee[p,q2]=x[4q2], xeo=x[4q2+2]; xo[p,q1]=x[2q1+1];
//   w[q1]=xo[q1]+xo[q1-1]; we[q2]=w[2q2], wo=w[2q2+1]; b[p]=x[p,4095]
// ---------------------------------------------------------------------------
__global__ void split_x2_kernel(const float* __restrict__ x) {
    int t = blockIdx.x * 256 + threadIdx.x;   // 4096*256 threads
    int p = t >> 8;
    int j = t & 255;
    const float* xr = x + (size_t)p * NDIM + 16 * j;
    float v[16];
    #pragma unroll
    for (int c = 0; c < 4; ++c) {
        float4 f = *(const float4*)(xr + 4 * c);
        v[4 * c] = f.x; v[4 * c + 1] = f.y; v[4 * c + 2] = f.z; v[4 * c + 3] = f.w;
    }
    float xm1 = (j > 0) ? xr[-1] : 0.0f;      // xo[p, 8j-1]

    float xo[8], w[8];
    #pragma unroll
    for (int k = 0; k < 8; ++k) xo[k] = v[2 * k + 1];
    w[0] = xo[0] + xm1;
    #pragma unroll
    for (int k = 1; k < 8; ++k) w[k] = xo[k] + xo[k - 1];

    size_t o4 = ((size_t)p << 10) + 4 * j;    // [4096 x 1024] offset
    size_t o8 = ((size_t)p << 11) + 8 * j;    // [4096 x 2048] offset
    uint32_t h, l;
    split_pair(v[0], v[4], h, l);
    *(uint32_t*)(g_op0h + o4) = h; *(uint32_t*)(g_op0l + o4) = l;
    split_pair(v[8], v[12], h, l);
    *(uint32_t*)(g_op0h + o4 + 2) = h; *(uint32_t*)(g_op0l + o4 + 2) = l;
    split_pair(v[2], v[6], h, l);
    *(uint32_t*)(g_op1h + o4) = h; *(uint32_t*)(g_op1l + o4) = l;
    split_pair(v[10], v[14], h, l);
    *(uint32_t*)(g_op1h + o4 + 2) = h; *(uint32_t*)(g_op1l + o4 + 2) = l;
    split_pair(w[0], w[2], h, l);
    *(uint32_t*)(g_op2h + o4) = h; *(uint32_t*)(g_op2l + o4) = l;
    split_pair(w[4], w[6], h, l);
    *(uint32_t*)(g_op2h + o4 + 2) = h; *(uint32_t*)(g_op2l + o4 + 2) = l;
    split_pair(w[1], w[3], h, l);
    *(uint32_t*)(g_op3h + o4) = h; *(uint32_t*)(g_op3l + o4) = l;
    split_pair(w[5], w[7], h, l);
    *(uint32_t*)(g_op3h + o4 + 2) = h; *(uint32_t*)(g_op3l + o4 + 2) = l;
    #pragma unroll
    for (int k = 0; k < 8; k += 2) {
        split_pair(xo[k], xo[k + 1], h, l);
        *(uint32_t*)(g_bigh + o8 + k) = h; *(uint32_t*)(g_bigl + o8 + k) = l;
    }
    if (j == 255) g_b[p] = v[15];
}

// ---------------------------------------------------------------------------
// GEMM core: D[m,n] = sum_k A[m,k]*B[n,k]; bf16 split x3; output ld = 4096.
// ---------------------------------------------------------------------------
template<int KTILES, int LDK>
__device__ __forceinline__ void gemm_core(
    const bf16* __restrict__ Ah, const bf16* __restrict__ Al,
    const bf16* __restrict__ Bh, const bf16* __restrict__ Bl,
    float* __restrict__ D, int m0, int n0) {
    extern __shared__ char smem[];
    const uint32_t sbase = smem_to_u32(smem);
    const int tid = threadIdx.x;
    const int lane = tid & 31;
    const int wid = tid >> 5;
    const int wm = wid & 3;
    const int wn = wid >> 2;

    const int lr = tid >> 2;
    const int lc = tid & 3;
    const bf16* gsrc[4] = {
        Ah + (size_t)(m0 + lr) * LDK + lc * 8,
        Al + (size_t)(m0 + lr) * LDK + lc * 8,
        Bh + (size_t)(n0 + lr) * LDK + lc * 8,
        Bl + (size_t)(n0 + lr) * LDK + lc * 8,
    };
    const uint32_t sdst =
        sbase + lr * ROWB + (uint32_t)((lc ^ ((lr >> 1) & 3)) << 4);

    const uint32_t lmask = (uint32_t)(((lane & 15) >> 1) & 3);
    const uint32_t soff0 = (uint32_t)(((lane >> 4) ^ lmask) << 4);
    const uint32_t soff1 = (uint32_t)(((2 + (lane >> 4)) ^ lmask) << 4);
    const uint32_t a_row = (uint32_t)((wm * 32 + (lane & 15)) * ROWB);
    const uint32_t b_row = (uint32_t)((wn * 64 + (lane & 15)) * ROWB);

    float acc[2][8][4];
    #pragma unroll
    for (int a = 0; a < 2; ++a)
        #pragma unroll
        for (int b = 0; b < 8; ++b)
            #pragma unroll
            for (int c = 0; c < 4; ++c) acc[a][b][c] = 0.0f;

    auto load_stage = [&](int stage, int kt) {
        #pragma unroll
        for (int p = 0; p < 4; ++p) {
            const bf16* s0 = gsrc[p] + kt * BK;
            uint32_t d = sdst + stage * STAGE_BYTES + p * PLANE_BYTES;
            CP_ASYNC16(d, s0);
            CP_ASYNC16(d + 64 * ROWB, s0 + (size_t)64 * LDK);
        }
    };

    load_stage(0, 0);
    CP_COMMIT();
    load_stage(1, 1);
    CP_COMMIT();

    int cs = 0, ls = 2;
    for (int kt = 0; kt < KTILES; ++kt) {
        CP_WAIT1();
        __syncthreads();
        if (kt + 2 < KTILES) load_stage(ls, kt + 2);
        CP_COMMIT();

        const uint32_t stg = sbase + cs * STAGE_BYTES;
        #pragma unroll
        for (int s = 0; s < 2; ++s) {
            const uint32_t soff = s ? soff1 : soff0;
            uint32_t ah[2][4], al[2][4];
            #pragma unroll
            for (int mt = 0; mt < 2; ++mt) {
                LDSM4(ah[mt], stg + a_row + mt * 1024 + soff);
                LDSM4(al[mt], stg + PLANE_BYTES + a_row + mt * 1024 + soff);
            }
            #pragma unroll
            for (int g = 0; g < 4; ++g) {
                uint32_t bh[4], bl[4];
                LDSM4(bh, stg + 2 * PLANE_BYTES + b_row + g * 1024 + soff);
                LDSM4(bl, stg + 3 * PLANE_BYTES + b_row + g * 1024 + soff);
                MMA16816(acc[0][2 * g],     ah[0], bh[0], bh[2]);
                MMA16816(acc[1][2 * g],     ah[1], bh[0], bh[2]);
                MMA16816(acc[0][2 * g + 1], ah[0], bh[1], bh[3]);
                MMA16816(acc[1][2 * g + 1], ah[1], bh[1], bh[3]);
                MMA16816(acc[0][2 * g],     al[0], bh[0], bh[2]);
                MMA16816(acc[1][2 * g],     al[1], bh[0], bh[2]);
                MMA16816(acc[0][2 * g + 1], al[0], bh[1], bh[3]);
                MMA16816(acc[1][2 * g + 1], al[1], bh[1], bh[3]);
                MMA16816(acc[0][2 * g],     ah[0], bl[0], bl[2]);
                MMA16816(acc[1][2 * g],     ah[1], bl[0], bl[2]);
                MMA16816(acc[0][2 * g + 1], ah[0], bl[1], bl[3]);
                MMA16816(acc[1][2 * g + 1], ah[1], bl[1], bl[3]);
            }
        }
        cs = (cs == 2) ? 0 : cs + 1;
        ls = (ls == 2) ? 0 : ls + 1;
    }

    const int r0 = m0 + wm * 32 + (lane >> 2);
    const int c0 = n0 + wn * 64 + (lane & 3) * 2;
    #pragma unroll
    for (int mt = 0; mt < 2; ++mt)
        #pragma unroll
        for (int nt = 0; nt < 8; ++nt) {
            int row = r0 + mt * 16;
            int col = c0 + nt * 8;
            *(float2*)&D[(size_t)row * NDIM + col] =
                make_float2(acc[mt][nt][0], acc[mt][nt][1]);
            *(float2*)&D[(size_t)(row + 8) * NDIM + col] =
                make_float2(acc[mt][nt][2], acc[mt][nt][3]);
        }
}

struct MainArgs {
    const bf16 *Ah[4], *Al[4], *Bh[4], *Bl[4];
    float* D[4];
};

// main: M=1024 (grid.y=8), N=4096 (grid.x=32), K=1024, z = operand set
__global__ void __launch_bounds__(256, 2) gemm_main_kernel(MainArgs a) {
    int z = blockIdx.z;
    gemm_core<32, 1024>(a.Ah[z], a.Al[z], a.Bh[z], a.Bl[z], a.D[z],
                        blockIdx.y * BM, blockIdx.x * BN);
}

// patch: M=128 (grid.y=1), N=4096, K=2048 split into 8 chunks (z), partial out
__global__ void __launch_bounds__(256, 2) gemm_patch_kernel(
    const bf16* Ah, const bf16* Al, const bf16* Bh, const bf16* Bl,
    float* Dpart) {
    int z = blockIdx.z;
    gemm_core<8, 2048>(Ah + z * 256, Al + z * 256, Bh + z * 256, Bl + z * 256,
                       Dpart + (size_t)z * PR * NDIM, 0, blockIdx.x * BN);
}

__global__ void patch_reduce_kernel() {
    int t = blockIdx.x * 256 + threadIdx.x;   // 131072 threads, float4 each
    size_t idx = (size_t)t * 4;
    float4 s = *(const float4*)(g_patchP + idx);
    #pragma unroll
    for (int z = 1; z < 8; ++z) {
        float4 v = *(const float4*)(g_patchP + (size_t)z * PR * NDIM + idx);
        s.x += v.x; s.y += v.y; s.z += v.z; s.w += v.w;
    }
    *(float4*)(g_patch + idx) = s;
}

// ---------------------------------------------------------------------------
// inner combine: T{g}[v] = E2+O2 ; T{g}[2047-v] = sign*(O2-E2)
//  sin: sign=+1 ; cos: sign=-1.   (G0,G1)->Ebuf, (G2,G3)->Zbuf
// ---------------------------------------------------------------------------
__global__ void inner_combine_kernel(float sign) {
    int t = blockIdx.x * 256 + threadIdx.x;   // 1024*1024 threads
    int v2 = t >> 10;
    int j = t & 1023;
    size_t gi = ((size_t)v2 << 12) + 4 * j;
    size_t lo = ((size_t)v2 << 12) + 4 * j;
    size_t hi = ((size_t)(2047 - v2) << 12) + 4 * j;
    float4 e = *(const float4*)(g_G0 + gi);
    float4 o = *(const float4*)(g_G1 + gi);
    *(float4*)(g_Ebuf + lo) = make_float4(e.x + o.x, e.y + o.y, e.z + o.z, e.w + o.w);
    *(float4*)(g_Ebuf + hi) = make_float4(sign * (o.x - e.x), sign * (o.y - e.y),
                                          sign * (o.z - e.z), sign * (o.w - e.w));
    e = *(const float4*)(g_G2 + gi);
    o = *(const float4*)(g_G3 + gi);
    *(float4*)(g_Zbuf + lo) = make_float4(e.x + o.x, e.y + o.y, e.z + o.z, e.w + o.w);
    *(float4*)(g_Zbuf + hi) = make_float4(sign * (o.x - e.x), sign * (o.y - e.y),
                                          sign * (o.z - e.z), sign * (o.w - e.w));
}

// ---------------------------------------------------------------------------
// outer combine, stage 1 (sin): produces Yt rows v and 4095-v, and directly
// emits stage-2 operands:
//   Ytee[vo,p2]=Yt[vo,4p2]  Yteo=Yt[4p2+2]  Yto[vo,p1]=Yt[2p1+1]
//   wc[p1]=Yto[p1]+Yto[p1-1]; wce=wc[2p2], wco=wc[2p2+1]
// ---------------------------------------------------------------------------
__device__ __forceinline__ void emit_row(int row, const float* yt, float ytn) {
    size_t o4 = ((size_t)row << 10);
    size_t o8 = ((size_t)row << 11);
    int j = -1; // filled by caller via yt offsets; see usage (o4/o8 adjusted there)
    (void)j;
    (void)o4; (void)o8; (void)yt; (void)ytn; (void)row;
}

__global__ void outer_combine1_kernel() {
    int t = blockIdx.x * 256 + threadIdx.x;   // 2048*256 threads
    int v = t >> 8;
    int j = t & 255;                          // p block [16j, 16j+16)
    size_t rowE = ((size_t)v << 12) + 16 * j;

    float E[16], O[16];
    #pragma unroll
    for (int c = 0; c < 4; ++c) {
        float4 f = *(const float4*)(g_Ebuf + rowE + 4 * c);
        E[4 * c] = f.x; E[4 * c + 1] = f.y; E[4 * c + 2] = f.z; E[4 * c + 3] = f.w;
    }
    float En = (j > 0) ? g_Ebuf[rowE - 1] : 0.0f;
    float On;
    if (v < V0) {
        float r = 0.5f / cospif((2.0f * v + 1.0f) * (1.0f / 8192.0f));
        float s = (v & 1) ? -1.0f : 1.0f;
        #pragma unroll
        for (int c = 0; c < 4; ++c) {
            float4 z = *(const float4*)(g_Zbuf + rowE + 4 * c);
            float4 b = *(const float4*)(g_b + 16 * j + 4 * c);
            O[4 * c]     = r * (z.x + s * b.x);
            O[4 * c + 1] = r * (z.y + s * b.y);
            O[4 * c + 2] = r * (z.z + s * b.z);
            O[4 * c + 3] = r * (z.w + s * b.w);
        }
        On = (j > 0) ? r * (g_Zbuf[rowE - 1] + s * g_b[16 * j - 1]) : 0.0f;
    } else {
        size_t rowP = ((size_t)(v - V0) << 12) + 16 * j;
        #pragma unroll
        for (int c = 0; c < 4; ++c) {
            float4 f = *(const float4*)(g_patch + rowP + 4 * c);
            O[4 * c] = f.x; O[4 * c + 1] = f.y; O[4 * c + 2] = f.z; O[4 * c + 3] = f.w;
        }
        On = (j > 0) ? g_patch[rowP - 1] : 0.0f;
    }

    // two output rows
    #pragma unroll
    for (int half = 0; half < 2; ++half) {
        int row = half ? (4095 - v) : v;
        float yt[16], ytn;
        if (half == 0) {
            #pragma unroll
            for (int m = 0; m < 16; ++m) yt[m] = E[m] + O[m];
            ytn = En + On;
        } else {
            #pragma unroll
            for (int m = 0; m < 16; ++m) yt[m] = O[m] - E[m];
            ytn = On - En;
        }
        // odd p -> Yto, wc
        float yto[8], wc[8];
        #pragma unroll
        for (int k = 0; k < 8; ++k) yto[k] = yt[2 * k + 1];
        wc[0] = yto[0] + ytn;   // ytn = Yt[row, 16j-1] = Yto[row, 8j-1]; j=0 -> 0
        #pragma unroll
        for (int k = 1; k < 8; ++k) wc[k] = yto[k] + yto[k - 1];

        size_t o4 = ((size_t)row << 10) + 4 * j;
        size_t o8 = ((size_t)row << 11) + 8 * j;
        uint32_t h, l;
        split_pair(yt[0], yt[4], h, l);
        *(uint32_t*)(g_op0h + o4) = h; *(uint32_t*)(g_op0l + o4) = l;
        split_pair(yt[8], yt[12], h, l);
        *(uint32_t*)(g_op0h + o4 + 2) = h; *(uint32_t*)(g_op0l + o4 + 2) = l;
        split_pair(yt[2], yt[6], h, l);
        *(uint32_t*)(g_op1h + o4) = h; *(uint32_t*)(g_op1l + o4) = l;
        split_pair(yt[10], yt[14], h, l);
        *(uint32_t*)(g_op1h + o4 + 2) = h; *(uint32_t*)(g_op1l + o4 + 2) = l;
        split_pair(wc[0], wc[2], h, l);
        *(uint32_t*)(g_op2h + o4) = h; *(uint32_t*)(g_op2l + o4) = l;
        split_pair(wc[4], wc[6], h, l);
        *(uint32_t*)(g_op2h + o4 + 2) = h; *(uint32_t*)(g_op2l + o4 + 2) = l;
        split_pair(wc[1], wc[3], h, l);
        *(uint32_t*)(g_op3h + o4) = h; *(uint32_t*)(g_op3l + o4) = l;
        split_pair(wc[5], wc[7], h, l);
        *(uint32_t*)(g_op3h + o4 + 2) = h; *(uint32_t*)(g_op3l + o4 + 2) = l;
        #pragma unroll
        for (int k = 0; k < 8; k += 2) {
            split_pair(yto[k], yto[k + 1], h, l);
            *(uint32_t*)(g_bigh + o8 + k) = h; *(uint32_t*)(g_bigl + o8 + k) = l;
        }
    }
}

// ---------------------------------------------------------------------------
// outer combine, stage 2 (cos, no boundary): out[u] = E+O ; out[4095-u] = E-O
// ---------------------------------------------------------------------------
__global__ void outer_combine2_kernel(float* __restrict__ out) {
    int t = blockIdx.x * 256 + threadIdx.x;   // 2048*1024 threads
    int u = t >> 10;
    int j = t & 1023;
    size_t rowE = ((size_t)u << 12) + 4 * j;
    float4 e = *(const float4*)(g_Ebuf + rowE);
    float4 o;
    if (u < V0) {
        float r = 0.5f / cospif((2.0f * u + 1.0f) * (1.0f / 8192.0f));
        float4 z = *(const float4*)(g_Zbuf + rowE);
        o = make_float4(r * z.x, r * z.y, r * z.z, r * z.w);
    } else {
        o = *(const float4*)(g_patch + ((size_t)(u - V0) << 12) + 4 * j);
    }
    *(float4*)(out + ((size_t)u << 12) + 4 * j) =
        make_float4(e.x + o.x, e.y + o.y, e.z + o.z, e.w + o.w);
    *(float4*)(out + ((size_t)(4095 - u) << 12) + 4 * j) =
        make_float4(e.x - o.x, e.y - o.y, e.z - o.z, e.w - o.w);
}

// ---------------------------------------------------------------------------
extern "C" void kernel_launch(void* const* d_in, const int* in_sizes, int n_in,
                              void* d_out, int out_size) {
    const float* x = (const float*)d_in[0];
    float* out = (float*)d_out;

    bf16 *op0h, *op0l, *op1h, *op1l, *op2h, *op2l, *op3h, *op3l;
    bf16 *bigh, *bigl;
    bf16 *Se2h, *Se2l, *So2h, *So2l, *Ce2h, *Ce2l, *Co2h, *Co2l;
    bf16 *SoPh, *SoPl, *CoPh, *CoPl;
    float *G0, *G1, *G2, *G3, *patchP;
    cudaGetSymbolAddress((void**)&op0h, g_op0h); cudaGetSymbolAddress((void**)&op0l, g_op0l);
    cudaGetSymbolAddress((void**)&op1h, g_op1h); cudaGetSymbolAddress((void**)&op1l, g_op1l);
    cudaGetSymbolAddress((void**)&op2h, g_op2h); cudaGetSymbolAddress((void**)&op2l, g_op2l);
    cudaGetSymbolAddress((void**)&op3h, g_op3h); cudaGetSymbolAddress((void**)&op3l, g_op3l);
    cudaGetSymbolAddress((void**)&bigh, g_bigh); cudaGetSymbolAddress((void**)&bigl, g_bigl);
    cudaGetSymbolAddress((void**)&Se2h, g_Se2h); cudaGetSymbolAddress((void**)&Se2l, g_Se2l);
    cudaGetSymbolAddress((void**)&So2h, g_So2h); cudaGetSymbolAddress((void**)&So2l, g_So2l);
    cudaGetSymbolAddress((void**)&Ce2h, g_Ce2h); cudaGetSymbolAddress((void**)&Ce2l, g_Ce2l);
    cudaGetSymbolAddress((void**)&Co2h, g_Co2h); cudaGetSymbolAddress((void**)&Co2l, g_Co2l);
    cudaGetSymbolAddress((void**)&SoPh, g_SoPh); cudaGetSymbolAddress((void**)&SoPl, g_SoPl);
    cudaGetSymbolAddress((void**)&CoPh, g_CoPh); cudaGetSymbolAddress((void**)&CoPl, g_CoPl);
    cudaGetSymbolAddress((void**)&G0, g_G0); cudaGetSymbolAddress((void**)&G1, g_G1);
    cudaGetSymbolAddress((void**)&G2, g_G2); cudaGetSymbolAddress((void**)&G3, g_G3);
    cudaGetSymbolAddress((void**)&patchP, g_patchP);

    cudaFuncSetAttribute(gemm_main_kernel,
                         cudaFuncAttributeMaxDynamicSharedMemorySize, SMEM_BYTES);
    cudaFuncSetAttribute(gemm_patch_kernel,
                         cudaFuncAttributeMaxDynamicSharedMemorySize, SMEM_BYTES);

    build_table_kernel<<<64, 256>>>();
    gen_basis_inner<<<(1024 * 512) / 256, 256>>>();
    gen_basis_patch<<<(PR * 1024) / 256, 256>>>();
    split_x2_kernel<<<(NDIM * 256) / 256, 256>>>(x);

    dim3 gmain(NDIM / BN, 1024 / BM, 4);   // 32 x 8 x 4
    dim3 gpatch(NDIM / BN, 1, 8);          // 32 x 1 x 8

    // ---- stage 1 (sin along q) ----
    MainArgs a1;
    a1.Ah[0] = Se2h; a1.Al[0] = Se2l; a1.Bh[0] = op0h; a1.Bl[0] = op0l; a1.D[0] = G0;
    a1.Ah[1] = So2h; a1.Al[1] = So2l; a1.Bh[1] = op1h; a1.Bl[1] = op1l; a1.D[1] = G1;
    a1.Ah[2] = Se2h; a1.Al[2] = Se2l; a1.Bh[2] = op2h; a1.Bl[2] = op2l; a1.D[2] = G2;
    a1.Ah[3] = So2h; a1.Al[3] = So2l; a1.Bh[3] = op3h; a1.Bl[3] = op3l; a1.D[3] = G3;
    gemm_main_kernel<<<gmain, 256, SMEM_BYTES>>>(a1);
    gemm_patch_kernel<<<gpatch, 256, SMEM_BYTES>>>(SoPh, SoPl, bigh, bigl, patchP);
    patch_reduce_kernel<<<(PR * NDIM / 4) / 256, 256>>>();
    inner_combine_kernel<<<(1024 * 1024) / 256, 256>>>(1.0f);
    outer_combine1_kernel<<<(2048 * 256) / 256, 256>>>();

    // ---- stage 2 (cos along p) ----
    MainArgs a2;
    a2.Ah[0] = Ce2h; a2.Al[0] = Ce2l; a2.Bh[0] = op0h; a2.Bl[0] = op0l; a2.D[0] = G0;
    a2.Ah[1] = Co2h; a2.Al[1] = Co2l; a2.Bh[1] = op1h; a2.Bl[1] = op1l; a2.D[1] = G1;
    a2.Ah[2] = Ce2h; a2.Al[2] = Ce2l; a2.Bh[2] = op2h; a2.Bl[2] = op2l; a2.D[2] = G2;
    a2.Ah[3] = Co2h; a2.Al[3] = Co2l; a2.Bh[3] = op3h; a2.Bl[3] = op3l; a2.D[3] = G3;
    gemm_main_kernel<<<gmain, 256, SMEM_BYTES>>>(a2);
    gemm_patch_kernel<<<gpatch, 256, SMEM_BYTES>>>(CoPh, CoPl, bigh, bigl, patchP);
    patch_reduce_kernel<<<(PR * NDIM / 4) / 256, 256>>>();
    inner_combine_kernel<<<(1024 * 1024) / 256, 256>>>(-1.0f);
    outer_combine2_kernel<<<(2048 * 1024) / 256, 256>>>(out);
}

// round 8
// speedup vs baseline: 3.7515x; 1.0878x over previous
#include <cuda_runtime.h>
#include <cuda_bf16.h>
#include <cstdint>

// ============================================================================
// IDCST2: out = C0 @ x @ S1^T, M=N=4096 fp32.  Plain-sm_103 tensor path
// (mma.sync m16n8k16 bf16 + ldmatrix + cp.async), 3-term bf16 split.
// R6: two-level fast transform via parity fold + Lee's identity; dense patch
//     GEMM for the last PR rows (r_v blowup control).
// R7: - inner_combine folded into outer combines (pure index mapping)
//     - patch split-K reduction folded into outer combines
//     - patch GEMM merged into the main GEMM launch (fills tail wave)
// ============================================================================

#define NDIM 4096
typedef __nv_bfloat16 bf16;

static constexpr int BM = 128;
static constexpr int BN = 128;
static constexpr int BK = 32;
static constexpr int V0 = 1920;           // patch start row
static constexpr int PR = 128;            // patch rows (2048 - V0)

static constexpr int ROWB        = 64;
static constexpr int PLANE_BYTES = 128 * ROWB;      // 8192
static constexpr int STAGE_BYTES = 4 * PLANE_BYTES; // 32768
static constexpr int SMEM_BYTES  = 3 * STAGE_BYTES; // 98304

// -------------------- device scratch ----------------------------------------
__device__ float g_table[16384];
// operands [4096 x 1024] bf16 h/l  (stage1: xee,xeo,we,wo ; stage2: Ytee,Yteo,wce,wco)
__device__ bf16 g_op0h[(size_t)NDIM * 1024]; __device__ bf16 g_op0l[(size_t)NDIM * 1024];
__device__ bf16 g_op1h[(size_t)NDIM * 1024]; __device__ bf16 g_op1l[(size_t)NDIM * 1024];
__device__ bf16 g_op2h[(size_t)NDIM * 1024]; __device__ bf16 g_op2l[(size_t)NDIM * 1024];
__device__ bf16 g_op3h[(size_t)NDIM * 1024]; __device__ bf16 g_op3l[(size_t)NDIM * 1024];
// big operand [4096 x 2048] bf16 h/l (stage1: xo ; stage2: Yto) for patch GEMM
__device__ bf16 g_bigh[(size_t)NDIM * 2048]; __device__ bf16 g_bigl[(size_t)NDIM * 2048];
__device__ float g_b[NDIM];               // boundary vector (stage 1 only)
// bases [1024 x 1024] bf16 h/l
__device__ bf16 g_Se2h[1024 * 1024]; __device__ bf16 g_Se2l[1024 * 1024];
__device__ bf16 g_So2h[1024 * 1024]; __device__ bf16 g_So2l[1024 * 1024];
__device__ bf16 g_Ce2h[1024 * 1024]; __device__ bf16 g_Ce2l[1024 * 1024];
__device__ bf16 g_Co2h[1024 * 1024]; __device__ bf16 g_Co2l[1024 * 1024];
// patch bases [128 x 2048] bf16 h/l
__device__ bf16 g_SoPh[PR * 2048]; __device__ bf16 g_SoPl[PR * 2048];
__device__ bf16 g_CoPh[PR * 2048]; __device__ bf16 g_CoPl[PR * 2048];
// GEMM outputs [1024 x 4096] fp32
__device__ float g_G0[(size_t)1024 * NDIM];
__device__ float g_G1[(size_t)1024 * NDIM];
__device__ float g_G2[(size_t)1024 * NDIM];
__device__ float g_G3[(size_t)1024 * NDIM];
// patch partials [8 x 128 x 4096]
__device__ float g_patchP[(size_t)8 * PR * NDIM];

// -------------------- helpers ------------------------------------------------
__device__ __forceinline__ uint32_t smem_to_u32(const void* p) {
    uint32_t a;
    asm("{ .reg .u64 t; cvta.to.shared.u64 t, %1; cvt.u32.u64 %0, t; }" : "=r"(a) : "l"(p));
    return a;
}

__device__ __forceinline__ void split_pair(float x, float y, uint32_t& h, uint32_t& l) {
    __nv_bfloat162 H = __floats2bfloat162_rn(x, y);
    float2 F = __bfloat1622float2(H);
    __nv_bfloat162 L = __floats2bfloat162_rn(x - F.x, y - F.y);
    h = *(uint32_t*)&H;
    l = *(uint32_t*)&L;
}

#define CP_ASYNC16(dst, src) \
    asm volatile("cp.async.cg.shared.global [%0], [%1], 16;" :: "r"(dst), "l"(src))
#define CP_COMMIT() asm volatile("cp.async.commit_group;" ::: "memory")
#define CP_WAIT1()  asm volatile("cp.async.wait_group 1;"  ::: "memory")

#define LDSM4(r, addr) \
    asm volatile("ldmatrix.sync.aligned.m8n8.x4.shared.b16 {%0,%1,%2,%3}, [%4];" \
                 : "=r"((r)[0]), "=r"((r)[1]), "=r"((r)[2]), "=r"((r)[3]) : "r"(addr))

#define MMA16816(d, a, b0, b1) \
    asm volatile("mma.sync.aligned.m16n8k16.row.col.f32.bf16.bf16.f32 " \
                 "{%0,%1,%2,%3}, {%4,%5,%6,%7}, {%8,%9}, {%0,%1,%2,%3};" \
                 : "+f"((d)[0]), "+f"((d)[1]), "+f"((d)[2]), "+f"((d)[3]) \
                 : "r"((a)[0]), "r"((a)[1]), "r"((a)[2]), "r"((a)[3]), "r"(b0), "r"(b1))

// ---------------------------------------------------------------------------
__global__ void build_table_kernel() {
    int r = blockIdx.x * 256 + threadIdx.x;
    float s, c;
    sincospif((float)r * (1.0f / 8192.0f), &s, &c);
    g_table[r] = s;
}

// inner bases: Se2[i,q]=sin(pi(2i+1)q/2048); So2[i,q]=sin(pi(2i+1)(2q+1)/4096)
__global__ void gen_basis_inner() {
    int t = blockIdx.x * 256 + threadIdx.x;   // 1024*512 threads
    int i = t >> 9;
    int j2 = (t & 511) << 1;
    int step = 4 * (2 * i + 1);
    int a0 = ((2 * i + 1) * 4 * j2) & 16383;
    int a1 = (a0 + step) & 16383;
    int b0 = (2 * (2 * i + 1) * (2 * j2 + 1)) & 16383;
    int b1 = (b0 + step) & 16383;
    size_t off = ((size_t)i << 10) + j2;
    uint32_t h, l;
    split_pair(g_table[a0], g_table[a1], h, l);
    *(uint32_t*)(g_Se2h + off) = h; *(uint32_t*)(g_Se2l + off) = l;
    split_pair(g_table[b0], g_table[b1], h, l);
    *(uint32_t*)(g_So2h + off) = h; *(uint32_t*)(g_So2l + off) = l;
    split_pair(g_table[(a0 + 4096) & 16383], g_table[(a1 + 4096) & 16383], h, l);
    *(uint32_t*)(g_Ce2h + off) = h; *(uint32_t*)(g_Ce2l + off) = l;
    split_pair(g_table[(b0 + 4096) & 16383], g_table[(b1 + 4096) & 16383], h, l);
    *(uint32_t*)(g_Co2h + off) = h; *(uint32_t*)(g_Co2l + off) = l;
}

// patch bases: SoP[i,q] = sin(pi(2(V0+i)+1)(2q+1)/8192), CoP = cos version
__global__ void gen_basis_patch() {
    int t = blockIdx.x * 256 + threadIdx.x;   // 128*1024 threads
    int i = t >> 10;
    int j2 = (t & 1023) << 1;
    int M = 2 * (V0 + i) + 1;
    int a0 = (M * (2 * j2 + 1)) & 16383;
    int a1 = (a0 + 2 * M) & 16383;
    size_t off = ((size_t)i << 11) + j2;
    uint32_t h, l;
    split_pair(g_table[a0], g_table[a1], h, l);
    *(uint32_t*)(g_SoPh + off) = h; *(uint32_t*)(g_SoPl + off) = l;
    split_pair(g_table[(a0 + 4096) & 16383], g_table[(a1 + 4096) & 16383], h, l);
    *(uint32_t*)(g_CoPh + off) = h; *(uint32_t*)(g_CoPl + off) = l;
}

// ---------------------------------------------------------------------------
__global__ void split_x2_kernel(const float* __restrict__ x) {
    int t = blockIdx.x * 256 + threadIdx.x;   // 4096*256 threads
    int p = t >> 8;
    int j = t & 255;
    const float* xr = x + (size_t)p * NDIM + 16 * j;
    float v[16];
    #pragma unroll
    for (int c = 0; c < 4; ++c) {
        float4 f = *(const float4*)(xr + 4 * c);
        v[4 * c] = f.x; v[4 * c + 1] = f.y; v[4 * c + 2] = f.z; v[4 * c + 3] = f.w;
    }
    float xm1 = (j > 0) ? xr[-1] : 0.0f;

    float xo[8], w[8];
    #pragma unroll
    for (int k = 0; k < 8; ++k) xo[k] = v[2 * k + 1];
    w[0] = xo[0] + xm1;
    #pragma unroll
    for (int k = 1; k < 8; ++k) w[k] = xo[k] + xo[k - 1];

    size_t o4 = ((size_t)p << 10) + 4 * j;
    size_t o8 = ((size_t)p << 11) + 8 * j;
    uint32_t h, l;
    split_pair(v[0], v[4], h, l);
    *(uint32_t*)(g_op0h + o4) = h; *(uint32_t*)(g_op0l + o4) = l;
    split_pair(v[8], v[12], h, l);
    *(uint32_t*)(g_op0h + o4 + 2) = h; *(uint32_t*)(g_op0l + o4 + 2) = l;
    split_pair(v[2], v[6], h, l);
    *(uint32_t*)(g_op1h + o4) = h; *(uint32_t*)(g_op1l + o4) = l;
    split_pair(v[10], v[14], h, l);
    *(uint32_t*)(g_op1h + o4 + 2) = h; *(uint32_t*)(g_op1l + o4 + 2) = l;
    split_pair(w[0], w[2], h, l);
    *(uint32_t*)(g_op2h + o4) = h; *(uint32_t*)(g_op2l + o4) = l;
    split_pair(w[4], w[6], h, l);
    *(uint32_t*)(g_op2h + o4 + 2) = h; *(uint32_t*)(g_op2l + o4 + 2) = l;
    split_pair(w[1], w[3], h, l);
    *(uint32_t*)(g_op3h + o4) = h; *(uint32_t*)(g_op3l + o4) = l;
    split_pair(w[5], w[7], h, l);
    *(uint32_t*)(g_op3h + o4 + 2) = h; *(uint32_t*)(g_op3l + o4 + 2) = l;
    #pragma unroll
    for (int k = 0; k < 8; k += 2) {
        split_pair(xo[k], xo[k + 1], h, l);
        *(uint32_t*)(g_bigh + o8 + k) = h; *(uint32_t*)(g_bigl + o8 + k) = l;
    }
    if (j == 255) g_b[p] = v[15];
}

// ---------------------------------------------------------------------------
// GEMM core: D[m,n] = sum_k A[m,k]*B[n,k]; bf16 split x3; output ld = 4096.
// ---------------------------------------------------------------------------
template<int KTILES, int LDK>
__device__ __forceinline__ void gemm_core(
    const bf16* __restrict__ Ah, const bf16* __restrict__ Al,
    const bf16* __restrict__ Bh, const bf16* __restrict__ Bl,
    float* __restrict__ D, int m0, int n0) {
    extern __shared__ char smem[];
    const uint32_t sbase = smem_to_u32(smem);
    const int tid = threadIdx.x;
    const int lane = tid & 31;
    const int wid = tid >> 5;
    const int wm = wid & 3;
    const int wn = wid >> 2;

    const int lr = tid >> 2;
    const int lc = tid & 3;
    const bf16* gsrc[4] = {
        Ah + (size_t)(m0 + lr) * LDK + lc * 8,
        Al + (size_t)(m0 + lr) * LDK + lc * 8,
        Bh + (size_t)(n0 + lr) * LDK + lc * 8,
        Bl + (size_t)(n0 + lr) * LDK + lc * 8,
    };
    const uint32_t sdst =
        sbase + lr * ROWB + (uint32_t)((lc ^ ((lr >> 1) & 3)) << 4);

    const uint32_t lmask = (uint32_t)(((lane & 15) >> 1) & 3);
    const uint32_t soff0 = (uint32_t)(((lane >> 4) ^ lmask) << 4);
    const uint32_t soff1 = (uint32_t)(((2 + (lane >> 4)) ^ lmask) << 4);
    const uint32_t a_row = (uint32_t)((wm * 32 + (lane & 15)) * ROWB);
    const uint32_t b_row = (uint32_t)((wn * 64 + (lane & 15)) * ROWB);

    float acc[2][8][4];
    #pragma unroll
    for (int a = 0; a < 2; ++a)
        #pragma unroll
        for (int b = 0; b < 8; ++b)
            #pragma unroll
            for (int c = 0; c < 4; ++c) acc[a][b][c] = 0.0f;

    auto load_stage = [&](int stage, int kt) {
        #pragma unroll
        for (int p = 0; p < 4; ++p) {
            const bf16* s0 = gsrc[p] + kt * BK;
            uint32_t d = sdst + stage * STAGE_BYTES + p * PLANE_BYTES;
            CP_ASYNC16(d, s0);
            CP_ASYNC16(d + 64 * ROWB, s0 + (size_t)64 * LDK);
        }
    };

    load_stage(0, 0);
    CP_COMMIT();
    load_stage(1, 1);
    CP_COMMIT();

    int cs = 0, ls = 2;
    for (int kt = 0; kt < KTILES; ++kt) {
        CP_WAIT1();
        __syncthreads();
        if (kt + 2 < KTILES) load_stage(ls, kt + 2);
        CP_COMMIT();

        const uint32_t stg = sbase + cs * STAGE_BYTES;
        #pragma unroll
        for (int s = 0; s < 2; ++s) {
            const uint32_t soff = s ? soff1 : soff0;
            uint32_t ah[2][4], al[2][4];
            #pragma unroll
            for (int mt = 0; mt < 2; ++mt) {
                LDSM4(ah[mt], stg + a_row + mt * 1024 + soff);
                LDSM4(al[mt], stg + PLANE_BYTES + a_row + mt * 1024 + soff);
            }
            #pragma unroll
            for (int g = 0; g < 4; ++g) {
                uint32_t bh[4], bl[4];
                LDSM4(bh, stg + 2 * PLANE_BYTES + b_row + g * 1024 + soff);
                LDSM4(bl, stg + 3 * PLANE_BYTES + b_row + g * 1024 + soff);
                MMA16816(acc[0][2 * g],     ah[0], bh[0], bh[2]);
                MMA16816(acc[1][2 * g],     ah[1], bh[0], bh[2]);
                MMA16816(acc[0][2 * g + 1], ah[0], bh[1], bh[3]);
                MMA16816(acc[1][2 * g + 1], ah[1], bh[1], bh[3]);
                MMA16816(acc[0][2 * g],     al[0], bh[0], bh[2]);
                MMA16816(acc[1][2 * g],     al[1], bh[0], bh[2]);
                MMA16816(acc[0][2 * g + 1], al[0], bh[1], bh[3]);
                MMA16816(acc[1][2 * g + 1], al[1], bh[1], bh[3]);
                MMA16816(acc[0][2 * g],     ah[0], bl[0], bl[2]);
                MMA16816(acc[1][2 * g],     ah[1], bl[0], bl[2]);
                MMA16816(acc[0][2 * g + 1], ah[0], bl[1], bl[3]);
                MMA16816(acc[1][2 * g + 1], ah[1], bl[1], bl[3]);
            }
        }
        cs = (cs == 2) ? 0 : cs + 1;
        ls = (ls == 2) ? 0 : ls + 1;
    }

    const int r0 = m0 + wm * 32 + (lane >> 2);
    const int c0 = n0 + wn * 64 + (lane & 3) * 2;
    #pragma unroll
    for (int mt = 0; mt < 2; ++mt)
        #pragma unroll
        for (int nt = 0; nt < 8; ++nt) {
            int row = r0 + mt * 16;
            int col = c0 + nt * 8;
            *(float2*)&D[(size_t)row * NDIM + col] =
                make_float2(acc[mt][nt][0], acc[mt][nt][1]);
            *(float2*)&D[(size_t)(row + 8) * NDIM + col] =
                make_float2(acc[mt][nt][2], acc[mt][nt][3]);
        }
}

struct FusedArgs {
    const bf16 *Ah[4], *Al[4], *Bh[4], *Bl[4];
    float* D[4];
    const bf16 *PAh, *PAl;     // patch basis [128 x 2048]
};

// Merged launch: bid<1024 -> main tiles (z=bid>>8, y=(bid>>5)&7, x=bid&31);
// bid>=1024 -> patch tiles (z=(bid-1024)>>5 k-chunk, x=(bid-1024)&31).
// Patch CTAs are short (8 k-tiles) and land in the tail wave.
__global__ void __launch_bounds__(256, 2) gemm_fused_kernel(FusedArgs a) {
    int bid = blockIdx.x;
    if (bid < 1024) {
        int z = bid >> 8;
        gemm_core<32, 1024>(a.Ah[z], a.Al[z], a.Bh[z], a.Bl[z], a.D[z],
                            ((bid >> 5) & 7) * BM, (bid & 31) * BN);
    } else {
        int p = bid - 1024;
        int z = p >> 5;
        float* patchP;
        asm("cvta.global.u64 %0, %1;" : "=l"(patchP) : "l"((void*)g_patchP));
        gemm_core<8, 2048>(a.PAh + z * 256, a.PAl + z * 256,
                           g_bigh + z * 256, g_bigl + z * 256,
                           g_patchP + (size_t)z * PR * NDIM, 0, (p & 31) * BN);
    }
}

// ---------------------------------------------------------------------------
// E/Z access with the mirror fold applied inline:
//   E(v,col) = a0*G0[vr,col] + a1*G1[vr,col],  vr = v<1024 ? v : 2047-v,
//   (a0,a1) = (1,1) if v<1024 else (-sign, sign).  Z uses G2/G3.
// Patch rows (v>=V0): O = sum over 8 split-K partials.
// ---------------------------------------------------------------------------
__global__ void outer_combine1_kernel() {
    int t = blockIdx.x * 256 + threadIdx.x;   // 2048*256 threads
    int v = t >> 8;
    int j = t & 255;                          // p block [16j, 16j+16)
    const float sign = 1.0f;                  // sin stage
    int vr = (v < 1024) ? v : 2047 - v;
    float a0 = (v < 1024) ? 1.0f : -sign;
    float a1 = (v < 1024) ? 1.0f : sign;
    size_t rowG = ((size_t)vr << 12) + 16 * j;

    float E[16], O[16];
    #pragma unroll
    for (int c = 0; c < 4; ++c) {
        float4 f0 = *(const float4*)(g_G0 + rowG + 4 * c);
        float4 f1 = *(const float4*)(g_G1 + rowG + 4 * c);
        E[4 * c]     = a0 * f0.x + a1 * f1.x;
        E[4 * c + 1] = a0 * f0.y + a1 * f1.y;
        E[4 * c + 2] = a0 * f0.z + a1 * f1.z;
        E[4 * c + 3] = a0 * f0.w + a1 * f1.w;
    }
    float En = (j > 0) ? (a0 * g_G0[rowG - 1] + a1 * g_G1[rowG - 1]) : 0.0f;
    float On;
    if (v < V0) {
        float r = 0.5f / cospif((2.0f * v + 1.0f) * (1.0f / 8192.0f));
        float s = (v & 1) ? -1.0f : 1.0f;
        #pragma unroll
        for (int c = 0; c < 4; ++c) {
            float4 f2 = *(const float4*)(g_G2 + rowG + 4 * c);
            float4 f3 = *(const float4*)(g_G3 + rowG + 4 * c);
            float4 b = *(const float4*)(g_b + 16 * j + 4 * c);
            O[4 * c]     = r * (a0 * f2.x + a1 * f3.x + s * b.x);
            O[4 * c + 1] = r * (a0 * f2.y + a1 * f3.y + s * b.y);
            O[4 * c + 2] = r * (a0 * f2.z + a1 * f3.z + s * b.z);
            O[4 * c + 3] = r * (a0 * f2.w + a1 * f3.w + s * b.w);
        }
        On = (j > 0)
           ? r * (a0 * g_G2[rowG - 1] + a1 * g_G3[rowG - 1] + s * g_b[16 * j - 1])
           : 0.0f;
    } else {
        size_t rowP = ((size_t)(v - V0) << 12) + 16 * j;
        #pragma unroll
        for (int m = 0; m < 16; ++m) O[m] = 0.0f;
        On = 0.0f;
        #pragma unroll
        for (int z = 0; z < 8; ++z) {
            size_t base = (size_t)z * PR * NDIM + rowP;
            #pragma unroll
            for (int c = 0; c < 4; ++c) {
                float4 f = *(const float4*)(g_patchP + base + 4 * c);
                O[4 * c] += f.x; O[4 * c + 1] += f.y;
                O[4 * c + 2] += f.z; O[4 * c + 3] += f.w;
            }
            if (j > 0) On += g_patchP[base - 1];
        }
    }

    #pragma unroll
    for (int half = 0; half < 2; ++half) {
        int row = half ? (4095 - v) : v;
        float yt[16], ytn;
        if (half == 0) {
            #pragma unroll
            for (int m = 0; m < 16; ++m) yt[m] = E[m] + O[m];
            ytn = En + On;
        } else {
            #pragma unroll
            for (int m = 0; m < 16; ++m) yt[m] = O[m] - E[m];
            ytn = On - En;
        }
        float yto[8], wc[8];
        #pragma unroll
        for (int k = 0; k < 8; ++k) yto[k] = yt[2 * k + 1];
        wc[0] = yto[0] + ytn;
        #pragma unroll
        for (int k = 1; k < 8; ++k) wc[k] = yto[k] + yto[k - 1];

        size_t o4 = ((size_t)row << 10) + 4 * j;
        size_t o8 = ((size_t)row << 11) + 8 * j;
        uint32_t h, l;
        split_pair(yt[0], yt[4], h, l);
        *(uint32_t*)(g_op0h + o4) = h; *(uint32_t*)(g_op0l + o4) = l;
        split_pair(yt[8], yt[12], h, l);
        *(uint32_t*)(g_op0h + o4 + 2) = h; *(uint32_t*)(g_op0l + o4 + 2) = l;
        split_pair(yt[2], yt[6], h, l);
        *(uint32_t*)(g_op1h + o4) = h; *(uint32_t*)(g_op1l + o4) = l;
        split_pair(yt[10], yt[14], h, l);
        *(uint32_t*)(g_op1h + o4 + 2) = h; *(uint32_t*)(g_op1l + o4 + 2) = l;
        split_pair(wc[0], wc[2], h, l);
        *(uint32_t*)(g_op2h + o4) = h; *(uint32_t*)(g_op2l + o4) = l;
        split_pair(wc[4], wc[6], h, l);
        *(uint32_t*)(g_op2h + o4 + 2) = h; *(uint32_t*)(g_op2l + o4 + 2) = l;
        split_pair(wc[1], wc[3], h, l);
        *(uint32_t*)(g_op3h + o4) = h; *(uint32_t*)(g_op3l + o4) = l;
        split_pair(wc[5], wc[7], h, l);
        *(uint32_t*)(g_op3h + o4 + 2) = h; *(uint32_t*)(g_op3l + o4 + 2) = l;
        #pragma unroll
        for (int k = 0; k < 8; k += 2) {
            split_pair(yto[k], yto[k + 1], h, l);
            *(uint32_t*)(g_bigh + o8 + k) = h; *(uint32_t*)(g_bigl + o8 + k) = l;
        }
    }
}

// stage 2 (cos, sign=-1, no boundary): out[u]=E+O; out[4095-u]=E-O
__global__ void outer_combine2_kernel(float* __restrict__ out) {
    int t = blockIdx.x * 256 + threadIdx.x;   // 2048*1024 threads
    int u = t >> 10;
    int j = t & 1023;
    const float sign = -1.0f;
    int ur = (u < 1024) ? u : 2047 - u;
    float a0 = (u < 1024) ? 1.0f : -sign;
    float a1 = (u < 1024) ? 1.0f : sign;
    size_t rowG = ((size_t)ur << 12) + 4 * j;

    float4 f0 = *(const float4*)(g_G0 + rowG);
    float4 f1 = *(const float4*)(g_G1 + rowG);
    float4 e = make_float4(a0 * f0.x + a1 * f1.x, a0 * f0.y + a1 * f1.y,
                           a0 * f0.z + a1 * f1.z, a0 * f0.w + a1 * f1.w);
    float4 o;
    if (u < V0) {
        float r = 0.5f / cospif((2.0f * u + 1.0f) * (1.0f / 8192.0f));
        float4 f2 = *(const float4*)(g_G2 + rowG);
        float4 f3 = *(const float4*)(g_G3 + rowG);
        o = make_float4(r * (a0 * f2.x + a1 * f3.x), r * (a0 * f2.y + a1 * f3.y),
                        r * (a0 * f2.z + a1 * f3.z), r * (a0 * f2.w + a1 * f3.w));
    } else {
        size_t rowP = ((size_t)(u - V0) << 12) + 4 * j;
        o = make_float4(0.f, 0.f, 0.f, 0.f);
        #pragma unroll
        for (int z = 0; z < 8; ++z) {
            float4 f = *(const float4*)(g_patchP + (size_t)z * PR * NDIM + rowP);
            o.x += f.x; o.y += f.y; o.z += f.z; o.w += f.w;
        }
    }
    *(float4*)(out + ((size_t)u << 12) + 4 * j) =
        make_float4(e.x + o.x, e.y + o.y, e.z + o.z, e.w + o.w);
    *(float4*)(out + ((size_t)(4095 - u) << 12) + 4 * j) =
        make_float4(e.x - o.x, e.y - o.y, e.z - o.z, e.w - o.w);
}

// ---------------------------------------------------------------------------
extern "C" void kernel_launch(void* const* d_in, const int* in_sizes, int n_in,
                              void* d_out, int out_size) {
    const float* x = (const float*)d_in[0];
    float* out = (float*)d_out;

    bf16 *op0h, *op0l, *op1h, *op1l, *op2h, *op2l, *op3h, *op3l;
    bf16 *Se2h, *Se2l, *So2h, *So2l, *Ce2h, *Ce2l, *Co2h, *Co2l;
    bf16 *SoPh, *SoPl, *CoPh, *CoPl;
    float *G0, *G1, *G2, *G3;
    cudaGetSymbolAddress((void**)&op0h, g_op0h); cudaGetSymbolAddress((void**)&op0l, g_op0l);
    cudaGetSymbolAddress((void**)&op1h, g_op1h); cudaGetSymbolAddress((void**)&op1l, g_op1l);
    cudaGetSymbolAddress((void**)&op2h, g_op2h); cudaGetSymbolAddress((void**)&op2l, g_op2l);
    cudaGetSymbolAddress((void**)&op3h, g_op3h); cudaGetSymbolAddress((void**)&op3l, g_op3l);
    cudaGetSymbolAddress((void**)&Se2h, g_Se2h); cudaGetSymbolAddress((void**)&Se2l, g_Se2l);
    cudaGetSymbolAddress((void**)&So2h, g_So2h); cudaGetSymbolAddress((void**)&So2l, g_So2l);
    cudaGetSymbolAddress((void**)&Ce2h, g_Ce2h); cudaGetSymbolAddress((void**)&Ce2l, g_Ce2l);
    cudaGetSymbolAddress((void**)&Co2h, g_Co2h); cudaGetSymbolAddress((void**)&Co2l, g_Co2l);
    cudaGetSymbolAddress((void**)&SoPh, g_SoPh); cudaGetSymbolAddress((void**)&SoPl, g_SoPl);
    cudaGetSymbolAddress((void**)&CoPh, g_CoPh); cudaGetSymbolAddress((void**)&CoPl, g_CoPl);
    cudaGetSymbolAddress((void**)&G0, g_G0); cudaGetSymbolAddress((void**)&G1, g_G1);
    cudaGetSymbolAddress((void**)&G2, g_G2); cudaGetSymbolAddress((void**)&G3, g_G3);

    cudaFuncSetAttribute(gemm_fused_kernel,
                         cudaFuncAttributeMaxDynamicSharedMemorySize, SMEM_BYTES);

    build_table_kernel<<<64, 256>>>();
    gen_basis_inner<<<(1024 * 512) / 256, 256>>>();
    gen_basis_patch<<<(PR * 1024) / 256, 256>>>();
    split_x2_kernel<<<(NDIM * 256) / 256, 256>>>(x);

    // ---- stage 1 (sin along q) ----
    FusedArgs a1;
    a1.Ah[0] = Se2h; a1.Al[0] = Se2l; a1.Bh[0] = op0h; a1.Bl[0] = op0l; a1.D[0] = G0;
    a1.Ah[1] = So2h; a1.Al[1] = So2l; a1.Bh[1] = op1h; a1.Bl[1] = op1l; a1.D[1] = G1;
    a1.Ah[2] = Se2h; a1.Al[2] = Se2l; a1.Bh[2] = op2h; a1.Bl[2] = op2l; a1.D[2] = G2;
    a1.Ah[3] = So2h; a1.Al[3] = So2l; a1.Bh[3] = op3h; a1.Bl[3] = op3l; a1.D[3] = G3;
    a1.PAh = SoPh; a1.PAl = SoPl;
    gemm_fused_kernel<<<1024 + 256, 256, SMEM_BYTES>>>(a1);
    outer_combine1_kernel<<<(2048 * 256) / 256, 256>>>();

    // ---- stage 2 (cos along p) ----
    FusedArgs a2;
    a2.Ah[0] = Ce2h; a2.Al[0] = Ce2l; a2.Bh[0] = op0h; a2.Bl[0] = op0l; a2.D[0] = G0;
    a2.Ah[1] = Co2h; a2.Al[1] = Co2l; a2.Bh[1] = op1h; a2.Bl[1] = op1l; a2.D[1] = G1;
    a2.Ah[2] = Ce2h; a2.Al[2] = Ce2l; a2.Bh[2] = op2h; a2.Bl[2] = op2l; a2.D[2] = G2;
    a2.Ah[3] = Co2h; a2.Al[3] = Co2l; a2.Bh[3] = op3h; a2.Bl[3] = op3l; a2.D[3] = G3;
    a2.PAh = CoPh; a2.PAl = CoPl;
    gemm_fused_kernel<<<1024 + 256, 256, SMEM_BYTES>>>(a2);
    outer_combine2_kernel<<<(2048 * 1024) / 256, 256>>>(out);
}

// round 9
// speedup vs baseline: 5.2355x; 1.3956x over previous
#include <cuda_runtime.h>
#include <cuda_fp16.h>
#include <cstdint>

// ============================================================================
// IDCST2: out = C0 @ x @ S1^T, M=N=4096 fp32.  Plain-sm_103 tensor path
// (mma.sync m16n8k16 f16 + ldmatrix + cp.async).
// R6/R7: two-level fast transform (parity fold + Lee), dense patch for the
//        last PR rows, fused combines, patch GEMM merged into main launch.
// R8: fp16 2-term split: basis = fp16 hi+lo (near exact), data = single fp16.
//     D = Ah*B + Al*B  (2 MMAs instead of 3; dropped A*(B-Bh) ~ 2^-11 noise,
//     inside budget since the TF32 reference itself carries 2.8e-4).
//     Stage = 3 planes x 8KB = 24KB -> 4-stage cp.async pipeline.
// ============================================================================

#define NDIM 4096
typedef __half f16;

static constexpr int BM = 128;
static constexpr int BN = 128;
static constexpr int BK = 32;
static constexpr int V0 = 1920;           // patch start row
static constexpr int PR = 128;            // patch rows (2048 - V0)

static constexpr int ROWB        = 64;              // 32 f16 = 64B rows
static constexpr int PLANE_BYTES = 128 * ROWB;      // 8192
static constexpr int STAGE_BYTES = 3 * PLANE_BYTES; // 24576 (Ah, Al, B)
static constexpr int NSTAGE      = 4;
static constexpr int SMEM_BYTES  = NSTAGE * STAGE_BYTES; // 98304

// -------------------- device scratch ----------------------------------------
__device__ float g_table[16384];
// data operands [4096 x 1024] f16 single plane
__device__ f16 g_op0[(size_t)NDIM * 1024];
__device__ f16 g_op1[(size_t)NDIM * 1024];
__device__ f16 g_op2[(size_t)NDIM * 1024];
__device__ f16 g_op3[(size_t)NDIM * 1024];
// big data operand [4096 x 2048] f16 (stage1: xo ; stage2: Yto) for patch
__device__ f16 g_big[(size_t)NDIM * 2048];
__device__ float g_b[NDIM];               // boundary vector (stage 1 only)
// bases [1024 x 1024] f16 h/l
__device__ f16 g_Se2h[1024 * 1024]; __device__ f16 g_Se2l[1024 * 1024];
__device__ f16 g_So2h[1024 * 1024]; __device__ f16 g_So2l[1024 * 1024];
__device__ f16 g_Ce2h[1024 * 1024]; __device__ f16 g_Ce2l[1024 * 1024];
__device__ f16 g_Co2h[1024 * 1024]; __device__ f16 g_Co2l[1024 * 1024];
// patch bases [128 x 2048] f16 h/l
__device__ f16 g_SoPh[PR * 2048]; __device__ f16 g_SoPl[PR * 2048];
__device__ f16 g_CoPh[PR * 2048]; __device__ f16 g_CoPl[PR * 2048];
// GEMM outputs [1024 x 4096] fp32
__device__ float g_G0[(size_t)1024 * NDIM];
__device__ float g_G1[(size_t)1024 * NDIM];
__device__ float g_G2[(size_t)1024 * NDIM];
__device__ float g_G3[(size_t)1024 * NDIM];
// patch partials [8 x 128 x 4096]
__device__ float g_patchP[(size_t)8 * PR * NDIM];

// -------------------- helpers ------------------------------------------------
__device__ __forceinline__ uint32_t smem_to_u32(const void* p) {
    uint32_t a;
    asm("{ .reg .u64 t; cvta.to.shared.u64 t, %1; cvt.u32.u64 %0, t; }" : "=r"(a) : "l"(p));
    return a;
}

// fp16 hi/lo split of a pair (for bases; near-exact 2-term representation)
__device__ __forceinline__ void split_pair_f16(float x, float y, uint32_t& h, uint32_t& l) {
    __half2 H = __floats2half2_rn(x, y);
    float2 F = __half22float2(H);
    __half2 L = __floats2half2_rn(x - F.x, y - F.y);
    h = *(uint32_t*)&H;
    l = *(uint32_t*)&L;
}

__device__ __forceinline__ uint32_t pack_h2(float x, float y) {
    __half2 H = __floats2half2_rn(x, y);
    return *(uint32_t*)&H;
}

#define CP_ASYNC16(dst, src) \
    asm volatile("cp.async.cg.shared.global [%0], [%1], 16;" :: "r"(dst), "l"(src))
#define CP_COMMIT() asm volatile("cp.async.commit_group;" ::: "memory")
#define CP_WAIT2()  asm volatile("cp.async.wait_group 2;"  ::: "memory")

#define LDSM4(r, addr) \
    asm volatile("ldmatrix.sync.aligned.m8n8.x4.shared.b16 {%0,%1,%2,%3}, [%4];" \
                 : "=r"((r)[0]), "=r"((r)[1]), "=r"((r)[2]), "=r"((r)[3]) : "r"(addr))

#define MMAF16(d, a, b0, b1) \
    asm volatile("mma.sync.aligned.m16n8k16.row.col.f32.f16.f16.f32 " \
                 "{%0,%1,%2,%3}, {%4,%5,%6,%7}, {%8,%9}, {%0,%1,%2,%3};" \
                 : "+f"((d)[0]), "+f"((d)[1]), "+f"((d)[2]), "+f"((d)[3]) \
                 : "r"((a)[0]), "r"((a)[1]), "r"((a)[2]), "r"((a)[3]), "r"(b0), "r"(b1))

// ---------------------------------------------------------------------------
__global__ void build_table_kernel() {
    int r = blockIdx.x * 256 + threadIdx.x;
    float s, c;
    sincospif((float)r * (1.0f / 8192.0f), &s, &c);
    g_table[r] = s;
}

// inner bases: Se2[i,q]=sin(pi(2i+1)q/2048); So2[i,q]=sin(pi(2i+1)(2q+1)/4096)
__global__ void gen_basis_inner() {
    int t = blockIdx.x * 256 + threadIdx.x;   // 1024*512 threads
    int i = t >> 9;
    int j2 = (t & 511) << 1;
    int step = 4 * (2 * i + 1);
    int a0 = ((2 * i + 1) * 4 * j2) & 16383;
    int a1 = (a0 + step) & 16383;
    int b0 = (2 * (2 * i + 1) * (2 * j2 + 1)) & 16383;
    int b1 = (b0 + step) & 16383;
    size_t off = ((size_t)i << 10) + j2;
    uint32_t h, l;
    split_pair_f16(g_table[a0], g_table[a1], h, l);
    *(uint32_t*)(g_Se2h + off) = h; *(uint32_t*)(g_Se2l + off) = l;
    split_pair_f16(g_table[b0], g_table[b1], h, l);
    *(uint32_t*)(g_So2h + off) = h; *(uint32_t*)(g_So2l + off) = l;
    split_pair_f16(g_table[(a0 + 4096) & 16383], g_table[(a1 + 4096) & 16383], h, l);
    *(uint32_t*)(g_Ce2h + off) = h; *(uint32_t*)(g_Ce2l + off) = l;
    split_pair_f16(g_table[(b0 + 4096) & 16383], g_table[(b1 + 4096) & 16383], h, l);
    *(uint32_t*)(g_Co2h + off) = h; *(uint32_t*)(g_Co2l + off) = l;
}

// patch bases: SoP[i,q] = sin(pi(2(V0+i)+1)(2q+1)/8192), CoP = cos version
__global__ void gen_basis_patch() {
    int t = blockIdx.x * 256 + threadIdx.x;   // 128*1024 threads
    int i = t >> 10;
    int j2 = (t & 1023) << 1;
    int M = 2 * (V0 + i) + 1;
    int a0 = (M * (2 * j2 + 1)) & 16383;
    int a1 = (a0 + 2 * M) & 16383;
    size_t off = ((size_t)i << 11) + j2;
    uint32_t h, l;
    split_pair_f16(g_table[a0], g_table[a1], h, l);
    *(uint32_t*)(g_SoPh + off) = h; *(uint32_t*)(g_SoPl + off) = l;
    split_pair_f16(g_table[(a0 + 4096) & 16383], g_table[(a1 + 4096) & 16383], h, l);
    *(uint32_t*)(g_CoPh + off) = h; *(uint32_t*)(g_CoPl + off) = l;
}

// ---------------------------------------------------------------------------
__global__ void split_x2_kernel(const float* __restrict__ x) {
    int t = blockIdx.x * 256 + threadIdx.x;   // 4096*256 threads
    int p = t >> 8;
    int j = t & 255;
    const float* xr = x + (size_t)p * NDIM + 16 * j;
    float v[16];
    #pragma unroll
    for (int c = 0; c < 4; ++c) {
        float4 f = *(const float4*)(xr + 4 * c);
        v[4 * c] = f.x; v[4 * c + 1] = f.y; v[4 * c + 2] = f.z; v[4 * c + 3] = f.w;
    }
    float xm1 = (j > 0) ? xr[-1] : 0.0f;

    float xo[8], w[8];
    #pragma unroll
    for (int k = 0; k < 8; ++k) xo[k] = v[2 * k + 1];
    w[0] = xo[0] + xm1;
    #pragma unroll
    for (int k = 1; k < 8; ++k) w[k] = xo[k] + xo[k - 1];

    size_t o4 = ((size_t)p << 10) + 4 * j;
    size_t o8 = ((size_t)p << 11) + 8 * j;
    *(uint32_t*)(g_op0 + o4)     = pack_h2(v[0], v[4]);
    *(uint32_t*)(g_op0 + o4 + 2) = pack_h2(v[8], v[12]);
    *(uint32_t*)(g_op1 + o4)     = pack_h2(v[2], v[6]);
    *(uint32_t*)(g_op1 + o4 + 2) = pack_h2(v[10], v[14]);
    *(uint32_t*)(g_op2 + o4)     = pack_h2(w[0], w[2]);
    *(uint32_t*)(g_op2 + o4 + 2) = pack_h2(w[4], w[6]);
    *(uint32_t*)(g_op3 + o4)     = pack_h2(w[1], w[3]);
    *(uint32_t*)(g_op3 + o4 + 2) = pack_h2(w[5], w[7]);
    #pragma unroll
    for (int k = 0; k < 8; k += 2)
        *(uint32_t*)(g_big + o8 + k) = pack_h2(xo[k], xo[k + 1]);
    if (j == 255) g_b[p] = v[15];
}

// ---------------------------------------------------------------------------
// GEMM core: D[m,n] = sum_k A[m,k]*B[n,k]; A = basis fp16 h+l, B = data fp16.
// 2 MMAs per (m,n,k16): Ah*B + Al*B.  4-stage cp.async pipeline, 1 sync/tile.
// smem swizzle (64B rows, 4x16B chunks): chunk ^= (row>>1)&3.
// ---------------------------------------------------------------------------
template<int KTILES, int LDK>
__device__ __forceinline__ void gemm_core(
    const f16* __restrict__ Ah, const f16* __restrict__ Al,
    const f16* __restrict__ B, float* __restrict__ D, int m0, int n0) {
    extern __shared__ char smem[];
    const uint32_t sbase = smem_to_u32(smem);
    const int tid = threadIdx.x;
    const int lane = tid & 31;
    const int wid = tid >> 5;
    const int wm = wid & 3;
    const int wn = wid >> 2;

    const int lr = tid >> 2;
    const int lc = tid & 3;
    const f16* gsrc[3] = {
        Ah + (size_t)(m0 + lr) * LDK + lc * 8,
        Al + (size_t)(m0 + lr) * LDK + lc * 8,
        B  + (size_t)(n0 + lr) * LDK + lc * 8,
    };
    const uint32_t sdst =
        sbase + lr * ROWB + (uint32_t)((lc ^ ((lr >> 1) & 3)) << 4);

    const uint32_t lmask = (uint32_t)(((lane & 15) >> 1) & 3);
    const uint32_t soff0 = (uint32_t)(((lane >> 4) ^ lmask) << 4);
    const uint32_t soff1 = (uint32_t)(((2 + (lane >> 4)) ^ lmask) << 4);
    const uint32_t a_row = (uint32_t)((wm * 32 + (lane & 15)) * ROWB);
    const uint32_t b_row = (uint32_t)((wn * 64 + (lane & 15)) * ROWB);

    float acc[2][8][4];
    #pragma unroll
    for (int a = 0; a < 2; ++a)
        #pragma unroll
        for (int b = 0; b < 8; ++b)
            #pragma unroll
            for (int c = 0; c < 4; ++c) acc[a][b][c] = 0.0f;

    auto load_stage = [&](int stage, int kt) {
        #pragma unroll
        for (int p = 0; p < 3; ++p) {
            const f16* s0 = gsrc[p] + kt * BK;
            uint32_t d = sdst + stage * STAGE_BYTES + p * PLANE_BYTES;
            CP_ASYNC16(d, s0);
            CP_ASYNC16(d + 64 * ROWB, s0 + (size_t)64 * LDK);
        }
    };

    load_stage(0, 0);
    CP_COMMIT();
    load_stage(1, 1);
    CP_COMMIT();
    load_stage(2, 2);
    CP_COMMIT();

    for (int kt = 0; kt < KTILES; ++kt) {
        CP_WAIT2();
        __syncthreads();
        // prefetch kt+3 into the stage computed during iter kt-1
        if (kt + 3 < KTILES) {
            load_stage((kt + 3) & 3, kt + 3);
            CP_COMMIT();
        }

        const uint32_t stg = sbase + (kt & 3) * STAGE_BYTES;
        #pragma unroll
        for (int s = 0; s < 2; ++s) {
            const uint32_t soff = s ? soff1 : soff0;
            uint32_t ah[2][4], al[2][4];
            #pragma unroll
            for (int mt = 0; mt < 2; ++mt) {
                LDSM4(ah[mt], stg + a_row + mt * 1024 + soff);
                LDSM4(al[mt], stg + PLANE_BYTES + a_row + mt * 1024 + soff);
            }
            #pragma unroll
            for (int g = 0; g < 4; ++g) {
                uint32_t bh[4];
                LDSM4(bh, stg + 2 * PLANE_BYTES + b_row + g * 1024 + soff);
                MMAF16(acc[0][2 * g],     ah[0], bh[0], bh[2]);
                MMAF16(acc[1][2 * g],     ah[1], bh[0], bh[2]);
                MMAF16(acc[0][2 * g + 1], ah[0], bh[1], bh[3]);
                MMAF16(acc[1][2 * g + 1], ah[1], bh[1], bh[3]);
                MMAF16(acc[0][2 * g],     al[0], bh[0], bh[2]);
                MMAF16(acc[1][2 * g],     al[1], bh[0], bh[2]);
                MMAF16(acc[0][2 * g + 1], al[0], bh[1], bh[3]);
                MMAF16(acc[1][2 * g + 1], al[1], bh[1], bh[3]);
            }
        }
    }

    const int r0 = m0 + wm * 32 + (lane >> 2);
    const int c0 = n0 + wn * 64 + (lane & 3) * 2;
    #pragma unroll
    for (int mt = 0; mt < 2; ++mt)
        #pragma unroll
        for (int nt = 0; nt < 8; ++nt) {
            int row = r0 + mt * 16;
            int col = c0 + nt * 8;
            *(float2*)&D[(size_t)row * NDIM + col] =
                make_float2(acc[mt][nt][0], acc[mt][nt][1]);
            *(float2*)&D[(size_t)(row + 8) * NDIM + col] =
                make_float2(acc[mt][nt][2], acc[mt][nt][3]);
        }
}

struct FusedArgs {
    const f16 *Ah[4], *Al[4], *B[4];
    float* D[4];
    const f16 *PAh, *PAl;     // patch basis [128 x 2048]
};

// Merged launch: bid<1024 -> main tiles; bid>=1024 -> patch split-K tiles.
__global__ void __launch_bounds__(256, 2) gemm_fused_kernel(FusedArgs a) {
    int bid = blockIdx.x;
    if (bid < 1024) {
        int z = bid >> 8;
        gemm_core<32, 1024>(a.Ah[z], a.Al[z], a.B[z], a.D[z],
                            ((bid >> 5) & 7) * BM, (bid & 31) * BN);
    } else {
        int p = bid - 1024;
        int z = p >> 5;
        gemm_core<8, 2048>(a.PAh + z * 256, a.PAl + z * 256,
                           g_big + z * 256,
                           g_patchP + (size_t)z * PR * NDIM, 0, (p & 31) * BN);
    }
}

// ---------------------------------------------------------------------------
// outer combine, stage 1 (sin):  E/Z read with mirror fold inline,
// emits Yt rows v & 4095-v directly as stage-2 fp16 operands.
// ---------------------------------------------------------------------------
__global__ void outer_combine1_kernel() {
    int t = blockIdx.x * 256 + threadIdx.x;   // 2048*256 threads
    int v = t >> 8;
    int j = t & 255;                          // p block [16j, 16j+16)
    const float sign = 1.0f;
    int vr = (v < 1024) ? v : 2047 - v;
    float a0 = (v < 1024) ? 1.0f : -sign;
    float a1 = (v < 1024) ? 1.0f : sign;
    size_t rowG = ((size_t)vr << 12) + 16 * j;

    float E[16], O[16];
    #pragma unroll
    for (int c = 0; c < 4; ++c) {
        float4 f0 = *(const float4*)(g_G0 + rowG + 4 * c);
        float4 f1 = *(const float4*)(g_G1 + rowG + 4 * c);
        E[4 * c]     = a0 * f0.x + a1 * f1.x;
        E[4 * c + 1] = a0 * f0.y + a1 * f1.y;
        E[4 * c + 2] = a0 * f0.z + a1 * f1.z;
        E[4 * c + 3] = a0 * f0.w + a1 * f1.w;
    }
    float En = (j > 0) ? (a0 * g_G0[rowG - 1] + a1 * g_G1[rowG - 1]) : 0.0f;
    float On;
    if (v < V0) {
        float r = 0.5f / cospif((2.0f * v + 1.0f) * (1.0f / 8192.0f));
        float s = (v & 1) ? -1.0f : 1.0f;
        #pragma unroll
        for (int c = 0; c < 4; ++c) {
            float4 f2 = *(const float4*)(g_G2 + rowG + 4 * c);
            float4 f3 = *(const float4*)(g_G3 + rowG + 4 * c);
            float4 b = *(const float4*)(g_b + 16 * j + 4 * c);
            O[4 * c]     = r * (a0 * f2.x + a1 * f3.x + s * b.x);
            O[4 * c + 1] = r * (a0 * f2.y + a1 * f3.y + s * b.y);
            O[4 * c + 2] = r * (a0 * f2.z + a1 * f3.z + s * b.z);
            O[4 * c + 3] = r * (a0 * f2.w + a1 * f3.w + s * b.w);
        }
        On = (j > 0)
           ? r * (a0 * g_G2[rowG - 1] + a1 * g_G3[rowG - 1] + s * g_b[16 * j - 1])
           : 0.0f;
    } else {
        size_t rowP = ((size_t)(v - V0) << 12) + 16 * j;
        #pragma unroll
        for (int m = 0; m < 16; ++m) O[m] = 0.0f;
        On = 0.0f;
        #pragma unroll
        for (int z = 0; z < 8; ++z) {
            size_t base = (size_t)z * PR * NDIM + rowP;
            #pragma unroll
            for (int c = 0; c < 4; ++c) {
                float4 f = *(const float4*)(g_patchP + base + 4 * c);
                O[4 * c] += f.x; O[4 * c + 1] += f.y;
                O[4 * c + 2] += f.z; O[4 * c + 3] += f.w;
            }
            if (j > 0) On += g_patchP[base - 1];
        }
    }

    #pragma unroll
    for (int half = 0; half < 2; ++half) {
        int row = half ? (4095 - v) : v;
        float yt[16], ytn;
        if (half == 0) {
            #pragma unroll
            for (int m = 0; m < 16; ++m) yt[m] = E[m] + O[m];
            ytn = En + On;
        } else {
            #pragma unroll
            for (int m = 0; m < 16; ++m) yt[m] = O[m] - E[m];
            ytn = On - En;
        }
        float yto[8], wc[8];
        #pragma unroll
        for (int k = 0; k < 8; ++k) yto[k] = yt[2 * k + 1];
        wc[0] = yto[0] + ytn;
        #pragma unroll
        for (int k = 1; k < 8; ++k) wc[k] = yto[k] + yto[k - 1];

        size_t o4 = ((size_t)row << 10) + 4 * j;
        size_t o8 = ((size_t)row << 11) + 8 * j;
        *(uint32_t*)(g_op0 + o4)     = pack_h2(yt[0], yt[4]);
        *(uint32_t*)(g_op0 + o4 + 2) = pack_h2(yt[8], yt[12]);
        *(uint32_t*)(g_op1 + o4)     = pack_h2(yt[2], yt[6]);
        *(uint32_t*)(g_op1 + o4 + 2) = pack_h2(yt[10], yt[14]);
        *(uint32_t*)(g_op2 + o4)     = pack_h2(wc[0], wc[2]);
        *(uint32_t*)(g_op2 + o4 + 2) = pack_h2(wc[4], wc[6]);
        *(uint32_t*)(g_op3 + o4)     = pack_h2(wc[1], wc[3]);
        *(uint32_t*)(g_op3 + o4 + 2) = pack_h2(wc[5], wc[7]);
        #pragma unroll
        for (int k = 0; k < 8; k += 2)
            *(uint32_t*)(g_big + o8 + k) = pack_h2(yto[k], yto[k + 1]);
    }
}

// stage 2 (cos, sign=-1, no boundary): out[u]=E+O; out[4095-u]=E-O
__global__ void outer_combine2_kernel(float* __restrict__ out) {
    int t = blockIdx.x * 256 + threadIdx.x;   // 2048*1024 threads
    int u = t >> 10;
    int j = t & 1023;
    const float sign = -1.0f;
    int ur = (u < 1024) ? u : 2047 - u;
    float a0 = (u < 1024) ? 1.0f : -sign;
    float a1 = (u < 1024) ? 1.0f : sign;
    size_t rowG = ((size_t)ur << 12) + 4 * j;

    float4 f0 = *(const float4*)(g_G0 + rowG);
    float4 f1 = *(const float4*)(g_G1 + rowG);
    float4 e = make_float4(a0 * f0.x + a1 * f1.x, a0 * f0.y + a1 * f1.y,
                           a0 * f0.z + a1 * f1.z, a0 * f0.w + a1 * f1.w);
    float4 o;
    if (u < V0) {
        float r = 0.5f / cospif((2.0f * u + 1.0f) * (1.0f / 8192.0f));
        float4 f2 = *(const float4*)(g_G2 + rowG);
        float4 f3 = *(const float4*)(g_G3 + rowG);
        o = make_float4(r * (a0 * f2.x + a1 * f3.x), r * (a0 * f2.y + a1 * f3.y),
                        r * (a0 * f2.z + a1 * f3.z), r * (a0 * f2.w + a1 * f3.w));
    } else {
        size_t rowP = ((size_t)(u - V0) << 12) + 4 * j;
        o = make_float4(0.f, 0.f, 0.f, 0.f);
        #pragma unroll
        for (int z = 0; z < 8; ++z) {
            float4 f = *(const float4*)(g_patchP + (size_t)z * PR * NDIM + rowP);
            o.x += f.x; o.y += f.y; o.z += f.z; o.w += f.w;
        }
    }
    *(float4*)(out + ((size_t)u << 12) + 4 * j) =
        make_float4(e.x + o.x, e.y + o.y, e.z + o.z, e.w + o.w);
    *(float4*)(out + ((size_t)(4095 - u) << 12) + 4 * j) =
        make_float4(e.x - o.x, e.y - o.y, e.z - o.z, e.w - o.w);
}

// ---------------------------------------------------------------------------
extern "C" void kernel_launch(void* const* d_in, const int* in_sizes, int n_in,
                              void* d_out, int out_size) {
    const float* x = (const float*)d_in[0];
    float* out = (float*)d_out;

    f16 *op0, *op1, *op2, *op3;
    f16 *Se2h, *Se2l, *So2h, *So2l, *Ce2h, *Ce2l, *Co2h, *Co2l;
    f16 *SoPh, *SoPl, *CoPh, *CoPl;
    float *G0, *G1, *G2, *G3;
    cudaGetSymbolAddress((void**)&op0, g_op0);
    cudaGetSymbolAddress((void**)&op1, g_op1);
    cudaGetSymbolAddress((void**)&op2, g_op2);
    cudaGetSymbolAddress((void**)&op3, g_op3);
    cudaGetSymbolAddress((void**)&Se2h, g_Se2h); cudaGetSymbolAddress((void**)&Se2l, g_Se2l);
    cudaGetSymbolAddress((void**)&So2h, g_So2h); cudaGetSymbolAddress((void**)&So2l, g_So2l);
    cudaGetSymbolAddress((void**)&Ce2h, g_Ce2h); cudaGetSymbolAddress((void**)&Ce2l, g_Ce2l);
    cudaGetSymbolAddress((void**)&Co2h, g_Co2h); cudaGetSymbolAddress((void**)&Co2l, g_Co2l);
    cudaGetSymbolAddress((void**)&SoPh, g_SoPh); cudaGetSymbolAddress((void**)&SoPl, g_SoPl);
    cudaGetSymbolAddress((void**)&CoPh, g_CoPh); cudaGetSymbolAddress((void**)&CoPl, g_CoPl);
    cudaGetSymbolAddress((void**)&G0, g_G0); cudaGetSymbolAddress((void**)&G1, g_G1);
    cudaGetSymbolAddress((void**)&G2, g_G2); cudaGetSymbolAddress((void**)&G3, g_G3);

    cudaFuncSetAttribute(gemm_fused_kernel,
                         cudaFuncAttributeMaxDynamicSharedMemorySize, SMEM_BYTES);

    build_table_kernel<<<64, 256>>>();
    gen_basis_inner<<<(1024 * 512) / 256, 256>>>();
    gen_basis_patch<<<(PR * 1024) / 256, 256>>>();
    split_x2_kernel<<<(NDIM * 256) / 256, 256>>>(x);

    // ---- stage 1 (sin along q) ----
    FusedArgs a1;
    a1.Ah[0] = Se2h; a1.Al[0] = Se2l; a1.B[0] = op0; a1.D[0] = G0;
    a1.Ah[1] = So2h; a1.Al[1] = So2l; a1.B[1] = op1; a1.D[1] = G1;
    a1.Ah[2] = Se2h; a1.Al[2] = Se2l; a1.B[2] = op2; a1.D[2] = G2;
    a1.Ah[3] = So2h; a1.Al[3] = So2l; a1.B[3] = op3; a1.D[3] = G3;
    a1.PAh = SoPh; a1.PAl = SoPl;
    gemm_fused_kernel<<<1024 + 256, 256, SMEM_BYTES>>>(a1);
    outer_combine1_kernel<<<(2048 * 256) / 256, 256>>>();

    // ---- stage 2 (cos along p) ----
    FusedArgs a2;
    a2.Ah[0] = Ce2h; a2.Al[0] = Ce2l; a2.B[0] = op0; a2.D[0] = G0;
    a2.Ah[1] = Co2h; a2.Al[1] = Co2l; a2.B[1] = op1; a2.D[1] = G1;
    a2.Ah[2] = Ce2h; a2.Al[2] = Ce2l; a2.B[2] = op2; a2.D[2] = G2;
    a2.Ah[3] = Co2h; a2.Al[3] = Co2l; a2.B[3] = op3; a2.D[3] = G3;
    a2.PAh = CoPh; a2.PAl = CoPl;
    gemm_fused_kernel<<<1024 + 256, 256, SMEM_BYTES>>>(a2);
    outer_combine2_kernel<<<(2048 * 1024) / 256, 256>>>(out);
}